// round 14
// baseline (speedup 1.0000x reference)
#include <cuda_runtime.h>
#include <cuda_fp16.h>
#include <cstdint>
#include <cstddef>

// ---------------------------------------------------------------------------
// Problem constants
// ---------------------------------------------------------------------------
#define BDIM 1024
#define SDIM 64
#define DDIM 768
#define POOLN 30
#define TOPK 4
#define SEQL 68          // TOPK + SDIM
#define CTOK 64
#define MROWS (BDIM*CTOK)    // 65536

#define OFF_RSIM (BDIM*CTOK*DDIM)               // 50331648
#define OFF_SIM  (OFF_RSIM + 1)                 // 50331649
#define OFF_IDX  (OFF_SIM + BDIM*POOLN)         // 50362369
#define OUT_TOTAL (OFF_IDX + BDIM*TOPK)         // 50366465

#define K2U32 384            // u32 per row of an fp16 matrix (768 fp16 / 2)
#define K2U4  96             // uint4 per row

// ---------------------------------------------------------------------------
// Scratch (static __device__ arrays — no runtime allocation)
// ---------------------------------------------------------------------------
__device__ float g_pnorm[POOLN * DDIM];
__device__ float g_xnorm[BDIM * DDIM];
__device__ int   g_idx[BDIM * TOPK];
__device__ float g_rsum[BDIM];
__device__ uint32_t g_buf16[(size_t)MROWS * K2U32];     // GEMM fp16 outputs
__device__ uint4 g_A16[(size_t)MROWS * K2U4];           // activation fp16
__device__ uint4 g_Wa16[DDIM * K2U4];                   // w2a^T fp16
__device__ uint4 g_Wb16[DDIM * K2U4];                   // w2b^T fp16

// mlp1 pre-transposed split-fp16 weights: (c, s/k) rows, 104 halves/row
#define M1SW  104
#define M1SWB 208
__device__ __align__(16) __half g_W1aTh[64 * M1SW];
__device__ __align__(16) __half g_W1aTl[64 * M1SW];
__device__ __align__(16) __half g_W1bTh[64 * M1SW];
__device__ __align__(16) __half g_W1bTl[64 * M1SW];

// ---------------------------------------------------------------------------
// helpers
// ---------------------------------------------------------------------------
__device__ __forceinline__ uint32_t smem_u32(const void* p) {
    uint32_t a;
    asm("{ .reg .u64 t; cvta.to.shared.u64 t, %1; cvt.u32.u64 %0, t; }"
        : "=r"(a) : "l"(p));
    return a;
}

__device__ __forceinline__ void ldsm_x4(uint32_t* r, uint32_t addr) {
    asm volatile("ldmatrix.sync.aligned.m8n8.x4.shared.b16 {%0,%1,%2,%3}, [%4];"
        : "=r"(r[0]), "=r"(r[1]), "=r"(r[2]), "=r"(r[3]) : "r"(addr));
}

__device__ __forceinline__ void mma_f16(float c[4], const uint32_t a[4],
                                        uint32_t b0, uint32_t b1) {
    asm volatile(
        "mma.sync.aligned.m16n8k16.row.col.f32.f16.f16.f32 "
        "{%0,%1,%2,%3}, {%4,%5,%6,%7}, {%8,%9}, {%0,%1,%2,%3};"
        : "+f"(c[0]), "+f"(c[1]), "+f"(c[2]), "+f"(c[3])
        : "r"(a[0]), "r"(a[1]), "r"(a[2]), "r"(a[3]), "r"(b0), "r"(b1));
}

__device__ __forceinline__ void cp16(uint32_t dst, const void* src) {
    asm volatile("cp.async.cg.shared.global [%0], [%1], 16;" :: "r"(dst), "l"(src));
}
#define CP_COMMIT() asm volatile("cp.async.commit_group;" ::: "memory")
#define CP_WAIT(n)  asm volatile("cp.async.wait_group %0;" :: "n"(n) : "memory")

// pack fp32 pair -> fp16x2
__device__ __forceinline__ uint32_t pack2h(float a, float b) {
    __half2 h = __floats2half2_rn(a, b);
    return *(uint32_t*)&h;
}

// ---------------------------------------------------------------------------
// K1: prompt_norm
// ---------------------------------------------------------------------------
__global__ __launch_bounds__(256) void pnorm_kernel(const float* __restrict__ prompt) {
    int p = blockIdx.x;
    int tid = threadIdx.x;
    const float* row = prompt + (size_t)p * DDIM;
    float v0 = row[tid], v1 = row[tid + 256], v2 = row[tid + 512];
    float ssq = v0 * v0 + v1 * v1 + v2 * v2;
    __shared__ float sh[8];
    #pragma unroll
    for (int o = 16; o; o >>= 1) ssq += __shfl_down_sync(0xffffffffu, ssq, o);
    if ((tid & 31) == 0) sh[tid >> 5] = ssq;
    __syncthreads();
    if (tid < 32) {
        float v = (tid < 8) ? sh[tid] : 0.f;
        #pragma unroll
        for (int o = 4; o; o >>= 1) v += __shfl_down_sync(0xffffffffu, v, o);
        if (tid == 0) sh[0] = v;
    }
    __syncthreads();
    float rn = rsqrtf(fmaxf(sh[0], 1e-12f));
    float* dst = g_pnorm + (size_t)p * DDIM;
    dst[tid]       = v0 * rn;
    dst[tid + 256] = v1 * rn;
    dst[tid + 512] = v2 * rn;
}

// ---------------------------------------------------------------------------
// K2: x_mean + l2 normalize
// ---------------------------------------------------------------------------
__global__ __launch_bounds__(256) void xmean_norm_kernel(const float* __restrict__ x) {
    int b = blockIdx.x;
    int tid = threadIdx.x;
    float m[3];
    float ssq = 0.f;
    #pragma unroll
    for (int i = 0; i < 3; i++) {
        int d = tid + i * 256;
        float s = 0.f;
        #pragma unroll 8
        for (int si = 0; si < SDIM; si++)
            s += x[((size_t)b * SDIM + si) * DDIM + d];
        m[i] = s * (1.f / SDIM);
        ssq += m[i] * m[i];
    }
    __shared__ float sh[8];
    #pragma unroll
    for (int o = 16; o; o >>= 1) ssq += __shfl_down_sync(0xffffffffu, ssq, o);
    if ((tid & 31) == 0) sh[tid >> 5] = ssq;
    __syncthreads();
    if (tid < 32) {
        float v = (tid < 8) ? sh[tid] : 0.f;
        #pragma unroll
        for (int o = 4; o; o >>= 1) v += __shfl_down_sync(0xffffffffu, v, o);
        if (tid == 0) sh[0] = v;
    }
    __syncthreads();
    float rn = rsqrtf(fmaxf(sh[0], 1e-12f));
    #pragma unroll
    for (int i = 0; i < 3; i++)
        g_xnorm[(size_t)b * DDIM + tid + i * 256] = m[i] * rn;
}

// ---------------------------------------------------------------------------
// K3: similarity + top-4 + per-batch reduce_sim partial
// ---------------------------------------------------------------------------
__global__ __launch_bounds__(256) void sim_topk_kernel(float* __restrict__ out, int write_aux) {
    int b = blockIdx.x;
    int tid = threadIdx.x;
    __shared__ float sx[DDIM];
    __shared__ float ssim[32];
    for (int i = tid; i < DDIM; i += 256) sx[i] = g_xnorm[(size_t)b * DDIM + i];
    __syncthreads();
    int p = tid >> 3;
    int l8 = tid & 7;
    float acc = 0.f;
    if (p < POOLN) {
        const float* pr = g_pnorm + (size_t)p * DDIM;
        for (int k = l8; k < DDIM; k += 8) acc += sx[k] * pr[k];
    }
    #pragma unroll
    for (int o = 4; o; o >>= 1) acc += __shfl_down_sync(0xffffffffu, acc, o, 8);
    if (l8 == 0 && p < POOLN) ssim[p] = acc;
    __syncthreads();
    if (write_aux && tid < POOLN) out[OFF_SIM + (size_t)b * POOLN + tid] = ssim[tid];
    if (tid == 0) {
        bool used[POOLN];
        #pragma unroll
        for (int i = 0; i < POOLN; i++) used[i] = false;
        float rs = 0.f;
        for (int k = 0; k < TOPK; k++) {
            int best = 0;
            float bv = -3.4e38f;
            for (int pp = 0; pp < POOLN; pp++) {
                if (!used[pp] && ssim[pp] > bv) { bv = ssim[pp]; best = pp; }
            }
            used[best] = true;
            g_idx[b * TOPK + k] = best;
            if (write_aux) out[OFF_IDX + (size_t)b * TOPK + k] = (float)best;
            rs += bv;
        }
        g_rsum[b] = rs;
    }
}

// ---------------------------------------------------------------------------
// K3b: reduce_sim scalar
// ---------------------------------------------------------------------------
__global__ __launch_bounds__(256) void reduce_rsim_kernel(float* __restrict__ out) {
    int tid = threadIdx.x;
    float v = g_rsum[tid] + g_rsum[tid + 256] + g_rsum[tid + 512] + g_rsum[tid + 768];
    __shared__ float sh[8];
    #pragma unroll
    for (int o = 16; o; o >>= 1) v += __shfl_down_sync(0xffffffffu, v, o);
    if ((tid & 31) == 0) sh[tid >> 5] = v;
    __syncthreads();
    if (tid < 32) {
        float w = (tid < 8) ? sh[tid] : 0.f;
        #pragma unroll
        for (int o = 4; o; o >>= 1) w += __shfl_down_sync(0xffffffffu, w, o);
        if (tid == 0) out[OFF_RSIM] = w * (1.f / BDIM);
    }
}

// ---------------------------------------------------------------------------
// K-wprep: transpose 768x768 weight into fp16 pairs.  grid (24,24), blk (32,8)
// ---------------------------------------------------------------------------
__global__ __launch_bounds__(256) void wprep_kernel(
    const float* __restrict__ W, uint32_t* __restrict__ W16)
{
    __shared__ float t[32][33];
    int bxn = blockIdx.x;   // n tile
    int byk = blockIdx.y;   // k tile
    int tx = threadIdx.x, ty = threadIdx.y;
    #pragma unroll
    for (int i = 0; i < 4; i++) {
        int k = byk * 32 + ty + i * 8;
        t[ty + i * 8][tx] = W[(size_t)k * DDIM + bxn * 32 + tx];
    }
    __syncthreads();
    int tid = ty * 32 + tx;
    #pragma unroll
    for (int q = 0; q < 2; q++) {
        int idx = tid + q * 256;
        int nn = idx >> 4;         // 0..31
        int p  = idx & 15;         // k-pair within tile
        size_t o = (size_t)(bxn * 32 + nn) * K2U32 + byk * 16 + p;
        W16[o] = pack2h(t[2 * p][nn], t[2 * p + 1][nn]);
    }
}

// ---------------------------------------------------------------------------
// K-w1prep: transpose + fp16-split mlp_1 weights into (c, s) rows of 104.
// grid=2 (0: w1a, 1: w1b), block=256.
// ---------------------------------------------------------------------------
__global__ __launch_bounds__(256) void w1prep_kernel(
    const float* __restrict__ w1a, const float* __restrict__ w1b)
{
    int sel = blockIdx.x;
    const float* src = sel ? w1b : w1a;
    int K = sel ? 64 : SEQL;
    __half* dh = sel ? g_W1bTh : g_W1aTh;
    __half* dl = sel ? g_W1bTl : g_W1aTl;
    for (int i = threadIdx.x; i < 64 * M1SW; i += 256) {
        int c = i / M1SW, s = i % M1SW;
        float v = (s < K) ? src[s * 64 + c] : 0.f;
        __half h = __float2half_rn(v);
        dh[i] = h;
        dl[i] = __float2half_rn(v - __half2float(h));
    }
}

// ---------------------------------------------------------------------------
// K4: fused mlp_1 (token mixing) — tensor-core, M=128 per block.
// grid = (6, B), block=256, 8 warps of 16(M)x64(N).
// LayerNorm fully in registers (quad shfl).  3 __syncthreads per block.
// ---------------------------------------------------------------------------
#define M1_A_H  0
#define M1_A_L  26624
#define M1_WA_H 53248
#define M1_WA_L 66560
#define M1_WB_H 79872
#define M1_WB_L 93184
#define M1_PAR  106496
#define M1_SMEM 108032
#define M1_ST   M1_WA_H          // 17408 needed, 26624 available

__global__ __launch_bounds__(256, 2) void mlp1_fused_kernel(
    const float* __restrict__ x_embed, const float* __restrict__ prompt,
    const float* __restrict__ b1a, const float* __restrict__ g1a,
    const float* __restrict__ be1a,
    const float* __restrict__ b1b, const float* __restrict__ g1b,
    const float* __restrict__ be1b)
{
    extern __shared__ char smx[];
    const uint32_t sbase = smem_u32(smx);
    __half* smAh = (__half*)(smx + M1_A_H);
    __half* smAl = (__half*)(smx + M1_A_L);
    float*  sPar = (float*)(smx + M1_PAR);
    __half* sT   = (__half*)(smx + M1_ST);

    const int b  = blockIdx.y;
    const int d0 = blockIdx.x * 128;
    const int tid = threadIdx.x;
    const int lane = tid & 31, wid = tid >> 5;
    const int warpM = wid * 16;
    const int g = lane >> 2, t4 = lane & 3;

    if (tid < 64) {
        sPar[tid]       = b1a[tid];
        sPar[64 + tid]  = g1a[tid];
        sPar[128 + tid] = be1a[tid];
        sPar[192 + tid] = b1b[tid];
        sPar[256 + tid] = g1b[tid];
        sPar[320 + tid] = be1b[tid];
    }
    {
        const uint4* s0 = (const uint4*)g_W1aTh;
        const uint4* s1 = (const uint4*)g_W1aTl;
        const uint4* s2 = (const uint4*)g_W1bTh;
        const uint4* s3 = (const uint4*)g_W1bTl;
        uint4* d0_ = (uint4*)(smx + M1_WA_H);
        uint4* d1_ = (uint4*)(smx + M1_WA_L);
        uint4* d2_ = (uint4*)(smx + M1_WB_H);
        uint4* d3_ = (uint4*)(smx + M1_WB_L);
        for (int i = tid; i < 832; i += 256) {
            d0_[i] = s0[i]; d1_[i] = s1[i]; d2_[i] = s2[i]; d3_[i] = s3[i];
        }
    }
    for (int i = tid; i < 128 * 28; i += 256) {
        int dd = i / 28, s = 68 + i % 28;
        smAh[dd * M1SW + s] = __ushort_as_half((unsigned short)0);
        smAl[dd * M1SW + s] = __ushort_as_half((unsigned short)0);
    }
    for (int i = tid; i < SEQL * 128; i += 256) {
        int s = i >> 7, dd = i & 127;
        float v;
        if (s < TOPK)
            v = prompt[(size_t)g_idx[b * TOPK + s] * DDIM + d0 + dd];
        else
            v = x_embed[((size_t)b * SDIM + (s - TOPK)) * DDIM + d0 + dd];
        __half h = __float2half_rn(v);
        smAh[dd * M1SW + s] = h;
        smAl[dd * M1SW + s] = __float2half_rn(v - __half2float(h));
    }
    __syncthreads();

    const uint32_t aoff = ((lane & 7) + ((lane >> 3) & 1) * 8) * M1SWB
                        + (lane >> 4) * 16;
    const uint32_t boff = (lane & 7) * M1SWB + (lane >> 3) * 16;
    const uint32_t sAh = sbase + M1_A_H + warpM * M1SWB;
    const uint32_t sAl = sbase + M1_A_L + warpM * M1SWB;

    float acc[8][4];
    #pragma unroll
    for (int ni = 0; ni < 8; ni++)
        #pragma unroll
        for (int e = 0; e < 4; e++) acc[ni][e] = 0.f;

    // ---- GEMM1: H1[d][c] = A^T @ W1a  (K=96 padded), 3-term split ----
    #pragma unroll
    for (int kb = 0; kb < 3; kb++) {
        uint32_t ah0[4], ah1[4], al0[4], al1[4];
        ldsm_x4(ah0, sAh + aoff + kb * 64);
        ldsm_x4(ah1, sAh + aoff + kb * 64 + 32);
        ldsm_x4(al0, sAl + aoff + kb * 64);
        ldsm_x4(al1, sAl + aoff + kb * 64 + 32);
        #pragma unroll
        for (int ni = 0; ni < 8; ni++) {
            uint32_t bh[4], bl[4];
            uint32_t ba = ni * 8 * M1SWB + boff + kb * 64;
            ldsm_x4(bh, sbase + M1_WA_H + ba);
            ldsm_x4(bl, sbase + M1_WA_L + ba);
            mma_f16(acc[ni], ah0, bh[0], bh[1]);
            mma_f16(acc[ni], ah0, bl[0], bl[1]);
            mma_f16(acc[ni], al0, bh[0], bh[1]);
            mma_f16(acc[ni], ah1, bh[2], bh[3]);
            mma_f16(acc[ni], ah1, bl[2], bl[3]);
            mma_f16(acc[ni], al1, bh[2], bh[3]);
        }
    }

    // ---- epilogue 1: bias+relu+LN in regs -> split fp16 back into A tiles ----
    {
        float s_lo = 0.f, sq_lo = 0.f, s_hi = 0.f, sq_hi = 0.f;
        #pragma unroll
        for (int ni = 0; ni < 8; ni++) {
            int c = ni * 8 + t4 * 2;
            float b0 = sPar[c], b1v = sPar[c + 1];
            acc[ni][0] = fmaxf(acc[ni][0] + b0, 0.f);
            acc[ni][1] = fmaxf(acc[ni][1] + b1v, 0.f);
            acc[ni][2] = fmaxf(acc[ni][2] + b0, 0.f);
            acc[ni][3] = fmaxf(acc[ni][3] + b1v, 0.f);
            s_lo += acc[ni][0] + acc[ni][1];
            sq_lo += acc[ni][0] * acc[ni][0] + acc[ni][1] * acc[ni][1];
            s_hi += acc[ni][2] + acc[ni][3];
            sq_hi += acc[ni][2] * acc[ni][2] + acc[ni][3] * acc[ni][3];
        }
        #pragma unroll
        for (int o = 1; o <= 2; o <<= 1) {
            s_lo  += __shfl_xor_sync(0xffffffffu, s_lo, o);
            sq_lo += __shfl_xor_sync(0xffffffffu, sq_lo, o);
            s_hi  += __shfl_xor_sync(0xffffffffu, s_hi, o);
            sq_hi += __shfl_xor_sync(0xffffffffu, sq_hi, o);
        }
        float m_lo = s_lo * (1.f / 64.f);
        float r_lo = rsqrtf(fmaxf(sq_lo * (1.f / 64.f) - m_lo * m_lo, 0.f) + 1e-5f);
        float m_hi = s_hi * (1.f / 64.f);
        float r_hi = rsqrtf(fmaxf(sq_hi * (1.f / 64.f) - m_hi * m_hi, 0.f) + 1e-5f);
        int row_lo = warpM + g, row_hi = warpM + 8 + g;
        #pragma unroll
        for (int ni = 0; ni < 8; ni++) {
            int c = ni * 8 + t4 * 2;
            float ga0 = sPar[64 + c], be0 = sPar[128 + c];
            float ga1 = sPar[64 + c + 1], be1v = sPar[128 + c + 1];
            float y0 = (acc[ni][0] - m_lo) * r_lo * ga0 + be0;
            float y1 = (acc[ni][1] - m_lo) * r_lo * ga1 + be1v;
            float y2 = (acc[ni][2] - m_hi) * r_hi * ga0 + be0;
            float y3 = (acc[ni][3] - m_hi) * r_hi * ga1 + be1v;
            uint32_t h01 = pack2h(y0, y1);
            __half2 hh = *(__half2*)&h01;
            uint32_t l01 = pack2h(y0 - __half2float(hh.x), y1 - __half2float(hh.y));
            uint32_t h23 = pack2h(y2, y3);
            __half2 hh2 = *(__half2*)&h23;
            uint32_t l23 = pack2h(y2 - __half2float(hh2.x), y3 - __half2float(hh2.y));
            *(uint32_t*)((char*)smAh + row_lo * M1SWB + c * 2) = h01;
            *(uint32_t*)((char*)smAl + row_lo * M1SWB + c * 2) = l01;
            *(uint32_t*)((char*)smAh + row_hi * M1SWB + c * 2) = h23;
            *(uint32_t*)((char*)smAl + row_hi * M1SWB + c * 2) = l23;
        }
    }
    __syncthreads();

    // ---- GEMM2: H2 = H1 @ W1b  (K=64), 3-term split ----
    #pragma unroll
    for (int ni = 0; ni < 8; ni++)
        #pragma unroll
        for (int e = 0; e < 4; e++) acc[ni][e] = 0.f;
    #pragma unroll
    for (int kb = 0; kb < 2; kb++) {
        uint32_t ah0[4], ah1[4], al0[4], al1[4];
        ldsm_x4(ah0, sAh + aoff + kb * 64);
        ldsm_x4(ah1, sAh + aoff + kb * 64 + 32);
        ldsm_x4(al0, sAl + aoff + kb * 64);
        ldsm_x4(al1, sAl + aoff + kb * 64 + 32);
        #pragma unroll
        for (int ni = 0; ni < 8; ni++) {
            uint32_t bh[4], bl[4];
            uint32_t ba = ni * 8 * M1SWB + boff + kb * 64;
            ldsm_x4(bh, sbase + M1_WB_H + ba);
            ldsm_x4(bl, sbase + M1_WB_L + ba);
            mma_f16(acc[ni], ah0, bh[0], bh[1]);
            mma_f16(acc[ni], ah0, bl[0], bl[1]);
            mma_f16(acc[ni], al0, bh[0], bh[1]);
            mma_f16(acc[ni], ah1, bh[2], bh[3]);
            mma_f16(acc[ni], ah1, bl[2], bl[3]);
            mma_f16(acc[ni], al1, bh[2], bh[3]);
        }
    }

    // ---- epilogue 2: bias+relu+LN in regs -> fp16 into transpose stage ----
    {
        float s_lo = 0.f, sq_lo = 0.f, s_hi = 0.f, sq_hi = 0.f;
        #pragma unroll
        for (int ni = 0; ni < 8; ni++) {
            int c = ni * 8 + t4 * 2;
            float b0 = sPar[192 + c], b1v = sPar[192 + c + 1];
            acc[ni][0] = fmaxf(acc[ni][0] + b0, 0.f);
            acc[ni][1] = fmaxf(acc[ni][1] + b1v, 0.f);
            acc[ni][2] = fmaxf(acc[ni][2] + b0, 0.f);
            acc[ni][3] = fmaxf(acc[ni][3] + b1v, 0.f);
            s_lo += acc[ni][0] + acc[ni][1];
            sq_lo += acc[ni][0] * acc[ni][0] + acc[ni][1] * acc[ni][1];
            s_hi += acc[ni][2] + acc[ni][3];
            sq_hi += acc[ni][2] * acc[ni][2] + acc[ni][3] * acc[ni][3];
        }
        #pragma unroll
        for (int o = 1; o <= 2; o <<= 1) {
            s_lo  += __shfl_xor_sync(0xffffffffu, s_lo, o);
            sq_lo += __shfl_xor_sync(0xffffffffu, sq_lo, o);
            s_hi  += __shfl_xor_sync(0xffffffffu, s_hi, o);
            sq_hi += __shfl_xor_sync(0xffffffffu, sq_hi, o);
        }
        float m_lo = s_lo * (1.f / 64.f);
        float r_lo = rsqrtf(fmaxf(sq_lo * (1.f / 64.f) - m_lo * m_lo, 0.f) + 1e-5f);
        float m_hi = s_hi * (1.f / 64.f);
        float r_hi = rsqrtf(fmaxf(sq_hi * (1.f / 64.f) - m_hi * m_hi, 0.f) + 1e-5f);
        int row_lo = warpM + g, row_hi = warpM + 8 + g;
        #pragma unroll
        for (int ni = 0; ni < 8; ni++) {
            int c = ni * 8 + t4 * 2;
            float ga0 = sPar[256 + c], be0 = sPar[320 + c];
            float ga1 = sPar[256 + c + 1], be1v = sPar[320 + c + 1];
            sT[c * 136 + row_lo]       = __float2half_rn((acc[ni][0] - m_lo) * r_lo * ga0 + be0);
            sT[(c + 1) * 136 + row_lo] = __float2half_rn((acc[ni][1] - m_lo) * r_lo * ga1 + be1v);
            sT[c * 136 + row_hi]       = __float2half_rn((acc[ni][2] - m_hi) * r_hi * ga0 + be0);
            sT[(c + 1) * 136 + row_hi] = __float2half_rn((acc[ni][3] - m_hi) * r_hi * ga1 + be1v);
        }
    }
    __syncthreads();

    uint32_t* A32 = (uint32_t*)g_A16;
    for (int i = tid; i < 4096; i += 256) {
        int c = i >> 6;
        int d2 = (i & 63) * 2;
        uint32_t v = *(uint32_t*)((char*)sT + (c * 136 + d2) * 2);
        A32[((size_t)b * CTOK + c) * K2U32 + (d0 >> 1) + (d2 >> 1)] = v;
    }
}

// ---------------------------------------------------------------------------
// K5/K7: fp16 mma.sync GEMM   C16 = fp16(relu(A @ W + bias))
//  4-stage cp.async pipeline, ONE __syncthreads per k-tile.
//  Output packed fp16 (halves write traffic vs fp32).
// ---------------------------------------------------------------------------
#define SSTRB 80                 // bytes per smem row (40 fp16)
#define TILEB (128 * SSTRB)      // 10240
#define STAGEB (2 * TILEB)       // 20480  (A tile + B tile)
#define NSTAGE 4
#define GEMM_SMEM (NSTAGE * STAGEB)   // 81920
#define NKT 24                   // 768 / 32

__global__ __launch_bounds__(256, 2) void gemm_f16_kernel(
    const uint4* __restrict__ A16, const uint4* __restrict__ B16,
    const float* __restrict__ bias, uint32_t* __restrict__ C16)
{
    extern __shared__ char smc[];
    const uint32_t sbase = smem_u32(smc);
    const int tid  = threadIdx.x;
    const int lane = tid & 31;
    const int wid  = tid >> 5;
    const int bx   = blockIdx.x;   // N tile (0..5)
    const int by   = blockIdx.y;   // M tile (0..511)

    const int warpM = (wid & 1) * 64;
    const int warpN = (wid >> 1) * 32;
    const int g  = lane >> 2;      // 0..7
    const int t4 = lane & 3;       // 0..3

    const int lrow = tid >> 1;            // 0..127
    const int ljj  = (tid & 1) * 2;       // 0 or 2
    const uint4* srcA = A16 + ((size_t)(by * 128) + lrow) * K2U4 + ljj;
    const uint4* srcB = B16 + ((size_t)(bx * 128) + lrow) * K2U4 + ljj;
    const uint32_t ldst = lrow * SSTRB + ljj * 16;

    const uint32_t aoff = ((lane & 7) + ((lane >> 3) & 1) * 8) * SSTRB
                        + (lane >> 4) * 16;                       // A (16-row blk)
    const uint32_t boff = (warpN + (lane & 7)) * SSTRB
                        + (lane >> 3) * 16;                       // B (x4: k0..31)

    float acc[4][4][4];
    #pragma unroll
    for (int mi = 0; mi < 4; mi++)
        #pragma unroll
        for (int ni = 0; ni < 4; ni++)
            #pragma unroll
            for (int e = 0; e < 4; e++) acc[mi][ni][e] = 0.f;

    #pragma unroll
    for (int s = 0; s < NSTAGE - 1; s++) {
        uint32_t sb = sbase + s * STAGEB + ldst;
        const uint4* pa = srcA + s * 4;
        const uint4* pb = srcB + s * 4;
        cp16(sb, pa);
        cp16(sb + 16, pa + 1);
        cp16(sb + TILEB, pb);
        cp16(sb + TILEB + 16, pb + 1);
        CP_COMMIT();
    }

    for (int t = 0; t < NKT; t++) {
        CP_WAIT(2);
        __syncthreads();

        if (t + NSTAGE - 1 < NKT) {
            uint32_t sb = sbase + ((t + NSTAGE - 1) & (NSTAGE - 1)) * STAGEB + ldst;
            const uint4* pa = srcA + (t + NSTAGE - 1) * 4;
            const uint4* pb = srcB + (t + NSTAGE - 1) * 4;
            cp16(sb, pa);
            cp16(sb + 16, pa + 1);
            cp16(sb + TILEB, pb);
            cp16(sb + TILEB + 16, pb + 1);
        }
        CP_COMMIT();

        const uint32_t Ab = sbase + (t & (NSTAGE - 1)) * STAGEB;
        const uint32_t Bb = Ab + TILEB;

        uint32_t bb[4][4];
        #pragma unroll
        for (int ni = 0; ni < 4; ni++)
            ldsm_x4(bb[ni], Bb + boff + ni * (8 * SSTRB));

        #pragma unroll
        for (int mi = 0; mi < 4; mi++) {
            uint32_t ro = (warpM + mi * 16) * SSTRB + aoff;
            uint32_t a0[4], a1[4];
            ldsm_x4(a0, Ab + ro);          // kk = 0
            ldsm_x4(a1, Ab + ro + 32);     // kk = 1
            #pragma unroll
            for (int ni = 0; ni < 4; ni++)
                mma_f16(acc[mi][ni], a0, bb[ni][0], bb[ni][1]);
            #pragma unroll
            for (int ni = 0; ni < 4; ni++)
                mma_f16(acc[mi][ni], a1, bb[ni][2], bb[ni][3]);
        }
    }

    // epilogue: bias + relu -> packed fp16
    #pragma unroll
    for (int mi = 0; mi < 4; mi++) {
        size_t row0 = (size_t)by * 128 + warpM + mi * 16 + g;
        #pragma unroll
        for (int ni = 0; ni < 4; ni++) {
            int col = bx * 128 + warpN + ni * 8 + t4 * 2;
            float b0 = bias[col], b1 = bias[col + 1];
            uint32_t p0 = pack2h(fmaxf(acc[mi][ni][0] + b0, 0.f),
                                 fmaxf(acc[mi][ni][1] + b1, 0.f));
            uint32_t p1 = pack2h(fmaxf(acc[mi][ni][2] + b0, 0.f),
                                 fmaxf(acc[mi][ni][3] + b1, 0.f));
            C16[row0 * K2U32 + (col >> 1)]       = p0;
            C16[(row0 + 8) * K2U32 + (col >> 1)] = p1;
        }
    }
}

// ---------------------------------------------------------------------------
// K6: LayerNorm over 768, fp16 in -> fp16 out (feeds next GEMM).  block=128
// ---------------------------------------------------------------------------
__global__ __launch_bounds__(128) void ln16_to16_kernel(
    const uint32_t* __restrict__ in16, uint32_t* __restrict__ out16,
    const float* __restrict__ g, const float* __restrict__ be)
{
    size_t row = blockIdx.x;
    int tid = threadIdx.x;
    const uint32_t* p = in16 + row * K2U32;
    uint32_t u0 = p[tid], u1 = p[tid + 128], u2 = p[tid + 256];
    float2 f0 = __half22float2(*(__half2*)&u0);
    float2 f1 = __half22float2(*(__half2*)&u1);
    float2 f2 = __half22float2(*(__half2*)&u2);
    float s  = f0.x + f0.y + f1.x + f1.y + f2.x + f2.y;
    float sq = f0.x*f0.x + f0.y*f0.y + f1.x*f1.x + f1.y*f1.y + f2.x*f2.x + f2.y*f2.y;
    __shared__ float sh[8];
    #pragma unroll
    for (int o = 16; o; o >>= 1) {
        s  += __shfl_down_sync(0xffffffffu, s, o);
        sq += __shfl_down_sync(0xffffffffu, sq, o);
    }
    if ((tid & 31) == 0) { sh[tid >> 5] = s; sh[4 + (tid >> 5)] = sq; }
    __syncthreads();
    if (tid < 32) {
        float a = (tid < 4) ? sh[tid] : 0.f;
        float c = (tid < 4) ? sh[4 + tid] : 0.f;
        #pragma unroll
        for (int o = 2; o; o >>= 1) {
            a += __shfl_down_sync(0xffffffffu, a, o);
            c += __shfl_down_sync(0xffffffffu, c, o);
        }
        if (tid == 0) { sh[0] = a; sh[1] = c; }
    }
    __syncthreads();
    float mean = sh[0] * (1.f / DDIM);
    float var  = sh[1] * (1.f / DDIM) - mean * mean;
    float rstd = rsqrtf(fmaxf(var, 0.f) + 1e-5f);
    uint32_t* q = out16 + row * K2U32;
    #pragma unroll
    for (int j = 0; j < 3; j++) {
        int pr = tid + j * 128;
        float2 f = (j == 0) ? f0 : (j == 1) ? f1 : f2;
        int c0 = 2 * pr;
        q[pr] = pack2h((f.x - mean) * rstd * g[c0] + be[c0],
                       (f.y - mean) * rstd * g[c0 + 1] + be[c0 + 1]);
    }
}

// ---------------------------------------------------------------------------
// K8: final LayerNorm, fp16 in -> fp32 out.  block=128
// ---------------------------------------------------------------------------
__global__ __launch_bounds__(128) void ln16_to32_kernel(
    const uint32_t* __restrict__ in16, float* __restrict__ out,
    const float* __restrict__ g, const float* __restrict__ be)
{
    size_t row = blockIdx.x;
    int tid = threadIdx.x;
    const uint32_t* p = in16 + row * K2U32;
    uint32_t u0 = p[tid], u1 = p[tid + 128], u2 = p[tid + 256];
    float2 f0 = __half22float2(*(__half2*)&u0);
    float2 f1 = __half22float2(*(__half2*)&u1);
    float2 f2 = __half22float2(*(__half2*)&u2);
    float s  = f0.x + f0.y + f1.x + f1.y + f2.x + f2.y;
    float sq = f0.x*f0.x + f0.y*f0.y + f1.x*f1.x + f1.y*f1.y + f2.x*f2.x + f2.y*f2.y;
    __shared__ float sh[8];
    #pragma unroll
    for (int o = 16; o; o >>= 1) {
        s  += __shfl_down_sync(0xffffffffu, s, o);
        sq += __shfl_down_sync(0xffffffffu, sq, o);
    }
    if ((tid & 31) == 0) { sh[tid >> 5] = s; sh[4 + (tid >> 5)] = sq; }
    __syncthreads();
    if (tid < 32) {
        float a = (tid < 4) ? sh[tid] : 0.f;
        float c = (tid < 4) ? sh[4 + tid] : 0.f;
        #pragma unroll
        for (int o = 2; o; o >>= 1) {
            a += __shfl_down_sync(0xffffffffu, a, o);
            c += __shfl_down_sync(0xffffffffu, c, o);
        }
        if (tid == 0) { sh[0] = a; sh[1] = c; }
    }
    __syncthreads();
    float mean = sh[0] * (1.f / DDIM);
    float var  = sh[1] * (1.f / DDIM) - mean * mean;
    float rstd = rsqrtf(fmaxf(var, 0.f) + 1e-5f);
    float* q = out + row * DDIM;
    #pragma unroll
    for (int j = 0; j < 3; j++) {
        int pr = tid + j * 128;
        float2 f = (j == 0) ? f0 : (j == 1) ? f1 : f2;
        int c0 = 2 * pr;
        float2 w;
        w.x = (f.x - mean) * rstd * g[c0] + be[c0];
        w.y = (f.y - mean) * rstd * g[c0 + 1] + be[c0 + 1];
        *(float2*)&q[c0] = w;
    }
}

// ---------------------------------------------------------------------------
// Launch
// ---------------------------------------------------------------------------
extern "C" void kernel_launch(void* const* d_in, const int* in_sizes, int n_in,
                              void* d_out, int out_size)
{
    const float* x_embed = (const float*)d_in[0];
    const float* prompt  = (const float*)d_in[1];
    const float* w1a  = (const float*)d_in[2];
    const float* b1a  = (const float*)d_in[3];
    const float* g1a  = (const float*)d_in[4];
    const float* be1a = (const float*)d_in[5];
    const float* w1b  = (const float*)d_in[6];
    const float* b1b  = (const float*)d_in[7];
    const float* g1b  = (const float*)d_in[8];
    const float* be1b = (const float*)d_in[9];
    const float* w2a  = (const float*)d_in[10];
    const float* b2a  = (const float*)d_in[11];
    const float* g2a  = (const float*)d_in[12];
    const float* be2a = (const float*)d_in[13];
    const float* w2b  = (const float*)d_in[14];
    const float* b2b  = (const float*)d_in[15];
    const float* g2b  = (const float*)d_in[16];
    const float* be2b = (const float*)d_in[17];
    float* out = (float*)d_out;

    int write_aux = (out_size >= OUT_TOTAL) ? 1 : 0;

    uint32_t* buf16 = nullptr;
    uint4 *A16, *Wa16, *Wb16;
    cudaGetSymbolAddress((void**)&buf16, g_buf16);
    cudaGetSymbolAddress((void**)&A16,  g_A16);
    cudaGetSymbolAddress((void**)&Wa16, g_Wa16);
    cudaGetSymbolAddress((void**)&Wb16, g_Wb16);

    // prompt selection pipeline
    pnorm_kernel<<<POOLN, 256>>>(prompt);
    xmean_norm_kernel<<<BDIM, 256>>>(x_embed);
    sim_topk_kernel<<<BDIM, 256>>>(out, write_aux);
    if (write_aux) reduce_rsim_kernel<<<1, 256>>>(out);

    // weight preps
    wprep_kernel<<<dim3(24, 24), dim3(32, 8)>>>(w2a, (uint32_t*)Wa16);
    wprep_kernel<<<dim3(24, 24), dim3(32, 8)>>>(w2b, (uint32_t*)Wb16);
    w1prep_kernel<<<2, 256>>>(w1a, w1b);

    // fused mlp_1 (tensor-core, M=128/block) -> fp16 activations
    cudaFuncSetAttribute(mlp1_fused_kernel,
                         cudaFuncAttributeMaxDynamicSharedMemorySize, M1_SMEM);
    mlp1_fused_kernel<<<dim3(DDIM / 128, BDIM), 256, M1_SMEM>>>(
        x_embed, prompt, b1a, g1a, be1a, b1b, g1b, be1b);

    // mlp_2: fp16 mma GEMM (fp16 out) + LN stages (fp16 in)
    cudaFuncSetAttribute(gemm_f16_kernel,
                         cudaFuncAttributeMaxDynamicSharedMemorySize, GEMM_SMEM);
    dim3 ggrid(DDIM / 128, MROWS / 128);   // (6, 512)
    gemm_f16_kernel<<<ggrid, 256, GEMM_SMEM>>>(A16, Wa16, b2a, buf16);
    ln16_to16_kernel<<<MROWS, 128>>>(buf16, (uint32_t*)A16, g2a, be2a);
    gemm_f16_kernel<<<ggrid, 256, GEMM_SMEM>>>(A16, Wb16, b2b, buf16);
    ln16_to32_kernel<<<MROWS, 128>>>(buf16, out, g2b, be2b);
}

// round 15
// speedup vs baseline: 1.4697x; 1.4697x over previous
#include <cuda_runtime.h>
#include <cuda_fp16.h>
#include <cstdint>
#include <cstddef>

// ---------------------------------------------------------------------------
// Problem constants
// ---------------------------------------------------------------------------
#define BDIM 1024
#define SDIM 64
#define DDIM 768
#define POOLN 30
#define TOPK 4
#define SEQL 68          // TOPK + SDIM
#define CTOK 64
#define MROWS (BDIM*CTOK)    // 65536

#define OFF_RSIM (BDIM*CTOK*DDIM)               // 50331648
#define OFF_SIM  (OFF_RSIM + 1)                 // 50331649
#define OFF_IDX  (OFF_SIM + BDIM*POOLN)         // 50362369
#define OUT_TOTAL (OFF_IDX + BDIM*TOPK)         // 50366465

#define K2U32 384            // u32 per row of an fp16 matrix (768 fp16 / 2)
#define K2U4  96             // uint4 per row

// ---------------------------------------------------------------------------
// Scratch (static __device__ arrays — no runtime allocation)
// ---------------------------------------------------------------------------
__device__ float g_pnorm[POOLN * DDIM];
__device__ float g_xnorm[BDIM * DDIM];
__device__ int   g_idx[BDIM * TOPK];
__device__ float g_rsum[BDIM];
__device__ float g_bufB[(size_t)MROWS * DDIM];          // GEMM fp32 outputs
__device__ uint4 g_A16[(size_t)MROWS * K2U4];           // activation fp16
__device__ uint4 g_Wa16[DDIM * K2U4];                   // w2a^T fp16
__device__ uint4 g_Wb16[DDIM * K2U4];                   // w2b^T fp16

// mlp1 pre-transposed split-fp16 weights: (c, s/k) rows, 104 halves/row
#define M1SW  104
#define M1SWB 208
__device__ __align__(16) __half g_W1aTh[64 * M1SW];
__device__ __align__(16) __half g_W1aTl[64 * M1SW];
__device__ __align__(16) __half g_W1bTh[64 * M1SW];
__device__ __align__(16) __half g_W1bTl[64 * M1SW];

// ---------------------------------------------------------------------------
// helpers
// ---------------------------------------------------------------------------
__device__ __forceinline__ uint32_t smem_u32(const void* p) {
    uint32_t a;
    asm("{ .reg .u64 t; cvta.to.shared.u64 t, %1; cvt.u32.u64 %0, t; }"
        : "=r"(a) : "l"(p));
    return a;
}

__device__ __forceinline__ void ldsm_x4(uint32_t* r, uint32_t addr) {
    asm volatile("ldmatrix.sync.aligned.m8n8.x4.shared.b16 {%0,%1,%2,%3}, [%4];"
        : "=r"(r[0]), "=r"(r[1]), "=r"(r[2]), "=r"(r[3]) : "r"(addr));
}

__device__ __forceinline__ void mma_f16(float c[4], const uint32_t a[4],
                                        uint32_t b0, uint32_t b1) {
    asm volatile(
        "mma.sync.aligned.m16n8k16.row.col.f32.f16.f16.f32 "
        "{%0,%1,%2,%3}, {%4,%5,%6,%7}, {%8,%9}, {%0,%1,%2,%3};"
        : "+f"(c[0]), "+f"(c[1]), "+f"(c[2]), "+f"(c[3])
        : "r"(a[0]), "r"(a[1]), "r"(a[2]), "r"(a[3]), "r"(b0), "r"(b1));
}

__device__ __forceinline__ void cp16(uint32_t dst, const void* src) {
    asm volatile("cp.async.cg.shared.global [%0], [%1], 16;" :: "r"(dst), "l"(src));
}
#define CP_COMMIT() asm volatile("cp.async.commit_group;" ::: "memory")
#define CP_WAIT(n)  asm volatile("cp.async.wait_group %0;" :: "n"(n) : "memory")

// pack fp32 pair -> fp16x2
__device__ __forceinline__ uint32_t pack2h(float a, float b) {
    __half2 h = __floats2half2_rn(a, b);
    return *(uint32_t*)&h;
}

// ---------------------------------------------------------------------------
// K1: prompt_norm
// ---------------------------------------------------------------------------
__global__ __launch_bounds__(256) void pnorm_kernel(const float* __restrict__ prompt) {
    int p = blockIdx.x;
    int tid = threadIdx.x;
    const float* row = prompt + (size_t)p * DDIM;
    float v0 = row[tid], v1 = row[tid + 256], v2 = row[tid + 512];
    float ssq = v0 * v0 + v1 * v1 + v2 * v2;
    __shared__ float sh[8];
    #pragma unroll
    for (int o = 16; o; o >>= 1) ssq += __shfl_down_sync(0xffffffffu, ssq, o);
    if ((tid & 31) == 0) sh[tid >> 5] = ssq;
    __syncthreads();
    if (tid < 32) {
        float v = (tid < 8) ? sh[tid] : 0.f;
        #pragma unroll
        for (int o = 4; o; o >>= 1) v += __shfl_down_sync(0xffffffffu, v, o);
        if (tid == 0) sh[0] = v;
    }
    __syncthreads();
    float rn = rsqrtf(fmaxf(sh[0], 1e-12f));
    float* dst = g_pnorm + (size_t)p * DDIM;
    dst[tid]       = v0 * rn;
    dst[tid + 256] = v1 * rn;
    dst[tid + 512] = v2 * rn;
}

// ---------------------------------------------------------------------------
// K2: x_mean + l2 normalize
// ---------------------------------------------------------------------------
__global__ __launch_bounds__(256) void xmean_norm_kernel(const float* __restrict__ x) {
    int b = blockIdx.x;
    int tid = threadIdx.x;
    float m[3];
    float ssq = 0.f;
    #pragma unroll
    for (int i = 0; i < 3; i++) {
        int d = tid + i * 256;
        float s = 0.f;
        #pragma unroll 8
        for (int si = 0; si < SDIM; si++)
            s += x[((size_t)b * SDIM + si) * DDIM + d];
        m[i] = s * (1.f / SDIM);
        ssq += m[i] * m[i];
    }
    __shared__ float sh[8];
    #pragma unroll
    for (int o = 16; o; o >>= 1) ssq += __shfl_down_sync(0xffffffffu, ssq, o);
    if ((tid & 31) == 0) sh[tid >> 5] = ssq;
    __syncthreads();
    if (tid < 32) {
        float v = (tid < 8) ? sh[tid] : 0.f;
        #pragma unroll
        for (int o = 4; o; o >>= 1) v += __shfl_down_sync(0xffffffffu, v, o);
        if (tid == 0) sh[0] = v;
    }
    __syncthreads();
    float rn = rsqrtf(fmaxf(sh[0], 1e-12f));
    #pragma unroll
    for (int i = 0; i < 3; i++)
        g_xnorm[(size_t)b * DDIM + tid + i * 256] = m[i] * rn;
}

// ---------------------------------------------------------------------------
// K3: similarity + top-4 + per-batch reduce_sim partial
// ---------------------------------------------------------------------------
__global__ __launch_bounds__(256) void sim_topk_kernel(float* __restrict__ out, int write_aux) {
    int b = blockIdx.x;
    int tid = threadIdx.x;
    __shared__ float sx[DDIM];
    __shared__ float ssim[32];
    for (int i = tid; i < DDIM; i += 256) sx[i] = g_xnorm[(size_t)b * DDIM + i];
    __syncthreads();
    int p = tid >> 3;
    int l8 = tid & 7;
    float acc = 0.f;
    if (p < POOLN) {
        const float* pr = g_pnorm + (size_t)p * DDIM;
        for (int k = l8; k < DDIM; k += 8) acc += sx[k] * pr[k];
    }
    #pragma unroll
    for (int o = 4; o; o >>= 1) acc += __shfl_down_sync(0xffffffffu, acc, o, 8);
    if (l8 == 0 && p < POOLN) ssim[p] = acc;
    __syncthreads();
    if (write_aux && tid < POOLN) out[OFF_SIM + (size_t)b * POOLN + tid] = ssim[tid];
    if (tid == 0) {
        bool used[POOLN];
        #pragma unroll
        for (int i = 0; i < POOLN; i++) used[i] = false;
        float rs = 0.f;
        for (int k = 0; k < TOPK; k++) {
            int best = 0;
            float bv = -3.4e38f;
            for (int pp = 0; pp < POOLN; pp++) {
                if (!used[pp] && ssim[pp] > bv) { bv = ssim[pp]; best = pp; }
            }
            used[best] = true;
            g_idx[b * TOPK + k] = best;
            if (write_aux) out[OFF_IDX + (size_t)b * TOPK + k] = (float)best;
            rs += bv;
        }
        g_rsum[b] = rs;
    }
}

// ---------------------------------------------------------------------------
// K3b: reduce_sim scalar
// ---------------------------------------------------------------------------
__global__ __launch_bounds__(256) void reduce_rsim_kernel(float* __restrict__ out) {
    int tid = threadIdx.x;
    float v = g_rsum[tid] + g_rsum[tid + 256] + g_rsum[tid + 512] + g_rsum[tid + 768];
    __shared__ float sh[8];
    #pragma unroll
    for (int o = 16; o; o >>= 1) v += __shfl_down_sync(0xffffffffu, v, o);
    if ((tid & 31) == 0) sh[tid >> 5] = v;
    __syncthreads();
    if (tid < 32) {
        float w = (tid < 8) ? sh[tid] : 0.f;
        #pragma unroll
        for (int o = 4; o; o >>= 1) w += __shfl_down_sync(0xffffffffu, w, o);
        if (tid == 0) out[OFF_RSIM] = w * (1.f / BDIM);
    }
}

// ---------------------------------------------------------------------------
// K-wprep: transpose 768x768 weight into fp16 pairs.  grid (24,24), blk (32,8)
// ---------------------------------------------------------------------------
__global__ __launch_bounds__(256) void wprep_kernel(
    const float* __restrict__ W, uint32_t* __restrict__ W16)
{
    __shared__ float t[32][33];
    int bxn = blockIdx.x;   // n tile
    int byk = blockIdx.y;   // k tile
    int tx = threadIdx.x, ty = threadIdx.y;
    #pragma unroll
    for (int i = 0; i < 4; i++) {
        int k = byk * 32 + ty + i * 8;
        t[ty + i * 8][tx] = W[(size_t)k * DDIM + bxn * 32 + tx];
    }
    __syncthreads();
    int tid = ty * 32 + tx;
    #pragma unroll
    for (int q = 0; q < 2; q++) {
        int idx = tid + q * 256;
        int nn = idx >> 4;         // 0..31
        int p  = idx & 15;         // k-pair within tile
        size_t o = (size_t)(bxn * 32 + nn) * K2U32 + byk * 16 + p;
        W16[o] = pack2h(t[2 * p][nn], t[2 * p + 1][nn]);
    }
}

// ---------------------------------------------------------------------------
// K-w1prep: transpose + fp16-split mlp_1 weights into (c, s) rows of 104.
// grid=2 (0: w1a, 1: w1b), block=256.
// ---------------------------------------------------------------------------
__global__ __launch_bounds__(256) void w1prep_kernel(
    const float* __restrict__ w1a, const float* __restrict__ w1b)
{
    int sel = blockIdx.x;
    const float* src = sel ? w1b : w1a;
    int K = sel ? 64 : SEQL;
    __half* dh = sel ? g_W1bTh : g_W1aTh;
    __half* dl = sel ? g_W1bTl : g_W1aTl;
    for (int i = threadIdx.x; i < 64 * M1SW; i += 256) {
        int c = i / M1SW, s = i % M1SW;
        float v = (s < K) ? src[s * 64 + c] : 0.f;
        __half h = __float2half_rn(v);
        dh[i] = h;
        dl[i] = __float2half_rn(v - __half2float(h));
    }
}

// ---------------------------------------------------------------------------
// K4: fused mlp_1 (token mixing) — tensor-core, M=128 per block.
// grid = (6, B), block=256, 8 warps of 16(M)x64(N).
// LayerNorm fully in registers (quad shfl).  3 __syncthreads per block.
// ---------------------------------------------------------------------------
#define M1_A_H  0
#define M1_A_L  26624
#define M1_WA_H 53248
#define M1_WA_L 66560
#define M1_WB_H 79872
#define M1_WB_L 93184
#define M1_PAR  106496
#define M1_SMEM 108032
#define M1_ST   M1_WA_H          // 17408 needed, 26624 available

__global__ __launch_bounds__(256, 2) void mlp1_fused_kernel(
    const float* __restrict__ x_embed, const float* __restrict__ prompt,
    const float* __restrict__ b1a, const float* __restrict__ g1a,
    const float* __restrict__ be1a,
    const float* __restrict__ b1b, const float* __restrict__ g1b,
    const float* __restrict__ be1b)
{
    extern __shared__ char smx[];
    const uint32_t sbase = smem_u32(smx);
    __half* smAh = (__half*)(smx + M1_A_H);
    __half* smAl = (__half*)(smx + M1_A_L);
    float*  sPar = (float*)(smx + M1_PAR);
    __half* sT   = (__half*)(smx + M1_ST);

    const int b  = blockIdx.y;
    const int d0 = blockIdx.x * 128;
    const int tid = threadIdx.x;
    const int lane = tid & 31, wid = tid >> 5;
    const int warpM = wid * 16;
    const int g = lane >> 2, t4 = lane & 3;

    if (tid < 64) {
        sPar[tid]       = b1a[tid];
        sPar[64 + tid]  = g1a[tid];
        sPar[128 + tid] = be1a[tid];
        sPar[192 + tid] = b1b[tid];
        sPar[256 + tid] = g1b[tid];
        sPar[320 + tid] = be1b[tid];
    }
    {
        const uint4* s0 = (const uint4*)g_W1aTh;
        const uint4* s1 = (const uint4*)g_W1aTl;
        const uint4* s2 = (const uint4*)g_W1bTh;
        const uint4* s3 = (const uint4*)g_W1bTl;
        uint4* d0_ = (uint4*)(smx + M1_WA_H);
        uint4* d1_ = (uint4*)(smx + M1_WA_L);
        uint4* d2_ = (uint4*)(smx + M1_WB_H);
        uint4* d3_ = (uint4*)(smx + M1_WB_L);
        for (int i = tid; i < 832; i += 256) {
            d0_[i] = s0[i]; d1_[i] = s1[i]; d2_[i] = s2[i]; d3_[i] = s3[i];
        }
    }
    for (int i = tid; i < 128 * 28; i += 256) {
        int dd = i / 28, s = 68 + i % 28;
        smAh[dd * M1SW + s] = __ushort_as_half((unsigned short)0);
        smAl[dd * M1SW + s] = __ushort_as_half((unsigned short)0);
    }
    for (int i = tid; i < SEQL * 128; i += 256) {
        int s = i >> 7, dd = i & 127;
        float v;
        if (s < TOPK)
            v = prompt[(size_t)g_idx[b * TOPK + s] * DDIM + d0 + dd];
        else
            v = x_embed[((size_t)b * SDIM + (s - TOPK)) * DDIM + d0 + dd];
        __half h = __float2half_rn(v);
        smAh[dd * M1SW + s] = h;
        smAl[dd * M1SW + s] = __float2half_rn(v - __half2float(h));
    }
    __syncthreads();

    const uint32_t aoff = ((lane & 7) + ((lane >> 3) & 1) * 8) * M1SWB
                        + (lane >> 4) * 16;
    const uint32_t boff = (lane & 7) * M1SWB + (lane >> 3) * 16;
    const uint32_t sAh = sbase + M1_A_H + warpM * M1SWB;
    const uint32_t sAl = sbase + M1_A_L + warpM * M1SWB;

    float acc[8][4];
    #pragma unroll
    for (int ni = 0; ni < 8; ni++)
        #pragma unroll
        for (int e = 0; e < 4; e++) acc[ni][e] = 0.f;

    // ---- GEMM1: H1[d][c] = A^T @ W1a  (K=96 padded), 3-term split ----
    #pragma unroll
    for (int kb = 0; kb < 3; kb++) {
        uint32_t ah0[4], ah1[4], al0[4], al1[4];
        ldsm_x4(ah0, sAh + aoff + kb * 64);
        ldsm_x4(ah1, sAh + aoff + kb * 64 + 32);
        ldsm_x4(al0, sAl + aoff + kb * 64);
        ldsm_x4(al1, sAl + aoff + kb * 64 + 32);
        #pragma unroll
        for (int ni = 0; ni < 8; ni++) {
            uint32_t bh[4], bl[4];
            uint32_t ba = ni * 8 * M1SWB + boff + kb * 64;
            ldsm_x4(bh, sbase + M1_WA_H + ba);
            ldsm_x4(bl, sbase + M1_WA_L + ba);
            mma_f16(acc[ni], ah0, bh[0], bh[1]);
            mma_f16(acc[ni], ah0, bl[0], bl[1]);
            mma_f16(acc[ni], al0, bh[0], bh[1]);
            mma_f16(acc[ni], ah1, bh[2], bh[3]);
            mma_f16(acc[ni], ah1, bl[2], bl[3]);
            mma_f16(acc[ni], al1, bh[2], bh[3]);
        }
    }

    // ---- epilogue 1: bias+relu+LN in regs -> split fp16 back into A tiles ----
    {
        float s_lo = 0.f, sq_lo = 0.f, s_hi = 0.f, sq_hi = 0.f;
        #pragma unroll
        for (int ni = 0; ni < 8; ni++) {
            int c = ni * 8 + t4 * 2;
            float b0 = sPar[c], b1v = sPar[c + 1];
            acc[ni][0] = fmaxf(acc[ni][0] + b0, 0.f);
            acc[ni][1] = fmaxf(acc[ni][1] + b1v, 0.f);
            acc[ni][2] = fmaxf(acc[ni][2] + b0, 0.f);
            acc[ni][3] = fmaxf(acc[ni][3] + b1v, 0.f);
            s_lo += acc[ni][0] + acc[ni][1];
            sq_lo += acc[ni][0] * acc[ni][0] + acc[ni][1] * acc[ni][1];
            s_hi += acc[ni][2] + acc[ni][3];
            sq_hi += acc[ni][2] * acc[ni][2] + acc[ni][3] * acc[ni][3];
        }
        #pragma unroll
        for (int o = 1; o <= 2; o <<= 1) {
            s_lo  += __shfl_xor_sync(0xffffffffu, s_lo, o);
            sq_lo += __shfl_xor_sync(0xffffffffu, sq_lo, o);
            s_hi  += __shfl_xor_sync(0xffffffffu, s_hi, o);
            sq_hi += __shfl_xor_sync(0xffffffffu, sq_hi, o);
        }
        float m_lo = s_lo * (1.f / 64.f);
        float r_lo = rsqrtf(fmaxf(sq_lo * (1.f / 64.f) - m_lo * m_lo, 0.f) + 1e-5f);
        float m_hi = s_hi * (1.f / 64.f);
        float r_hi = rsqrtf(fmaxf(sq_hi * (1.f / 64.f) - m_hi * m_hi, 0.f) + 1e-5f);
        int row_lo = warpM + g, row_hi = warpM + 8 + g;
        #pragma unroll
        for (int ni = 0; ni < 8; ni++) {
            int c = ni * 8 + t4 * 2;
            float ga0 = sPar[64 + c], be0 = sPar[128 + c];
            float ga1 = sPar[64 + c + 1], be1v = sPar[128 + c + 1];
            float y0 = (acc[ni][0] - m_lo) * r_lo * ga0 + be0;
            float y1 = (acc[ni][1] - m_lo) * r_lo * ga1 + be1v;
            float y2 = (acc[ni][2] - m_hi) * r_hi * ga0 + be0;
            float y3 = (acc[ni][3] - m_hi) * r_hi * ga1 + be1v;
            uint32_t h01 = pack2h(y0, y1);
            __half2 hh = *(__half2*)&h01;
            uint32_t l01 = pack2h(y0 - __half2float(hh.x), y1 - __half2float(hh.y));
            uint32_t h23 = pack2h(y2, y3);
            __half2 hh2 = *(__half2*)&h23;
            uint32_t l23 = pack2h(y2 - __half2float(hh2.x), y3 - __half2float(hh2.y));
            *(uint32_t*)((char*)smAh + row_lo * M1SWB + c * 2) = h01;
            *(uint32_t*)((char*)smAl + row_lo * M1SWB + c * 2) = l01;
            *(uint32_t*)((char*)smAh + row_hi * M1SWB + c * 2) = h23;
            *(uint32_t*)((char*)smAl + row_hi * M1SWB + c * 2) = l23;
        }
    }
    __syncthreads();

    // ---- GEMM2: H2 = H1 @ W1b  (K=64), 3-term split ----
    #pragma unroll
    for (int ni = 0; ni < 8; ni++)
        #pragma unroll
        for (int e = 0; e < 4; e++) acc[ni][e] = 0.f;
    #pragma unroll
    for (int kb = 0; kb < 2; kb++) {
        uint32_t ah0[4], ah1[4], al0[4], al1[4];
        ldsm_x4(ah0, sAh + aoff + kb * 64);
        ldsm_x4(ah1, sAh + aoff + kb * 64 + 32);
        ldsm_x4(al0, sAl + aoff + kb * 64);
        ldsm_x4(al1, sAl + aoff + kb * 64 + 32);
        #pragma unroll
        for (int ni = 0; ni < 8; ni++) {
            uint32_t bh[4], bl[4];
            uint32_t ba = ni * 8 * M1SWB + boff + kb * 64;
            ldsm_x4(bh, sbase + M1_WB_H + ba);
            ldsm_x4(bl, sbase + M1_WB_L + ba);
            mma_f16(acc[ni], ah0, bh[0], bh[1]);
            mma_f16(acc[ni], ah0, bl[0], bl[1]);
            mma_f16(acc[ni], al0, bh[0], bh[1]);
            mma_f16(acc[ni], ah1, bh[2], bh[3]);
            mma_f16(acc[ni], ah1, bl[2], bl[3]);
            mma_f16(acc[ni], al1, bh[2], bh[3]);
        }
    }

    // ---- epilogue 2: bias+relu+LN in regs -> fp16 into transpose stage ----
    {
        float s_lo = 0.f, sq_lo = 0.f, s_hi = 0.f, sq_hi = 0.f;
        #pragma unroll
        for (int ni = 0; ni < 8; ni++) {
            int c = ni * 8 + t4 * 2;
            float b0 = sPar[192 + c], b1v = sPar[192 + c + 1];
            acc[ni][0] = fmaxf(acc[ni][0] + b0, 0.f);
            acc[ni][1] = fmaxf(acc[ni][1] + b1v, 0.f);
            acc[ni][2] = fmaxf(acc[ni][2] + b0, 0.f);
            acc[ni][3] = fmaxf(acc[ni][3] + b1v, 0.f);
            s_lo += acc[ni][0] + acc[ni][1];
            sq_lo += acc[ni][0] * acc[ni][0] + acc[ni][1] * acc[ni][1];
            s_hi += acc[ni][2] + acc[ni][3];
            sq_hi += acc[ni][2] * acc[ni][2] + acc[ni][3] * acc[ni][3];
        }
        #pragma unroll
        for (int o = 1; o <= 2; o <<= 1) {
            s_lo  += __shfl_xor_sync(0xffffffffu, s_lo, o);
            sq_lo += __shfl_xor_sync(0xffffffffu, sq_lo, o);
            s_hi  += __shfl_xor_sync(0xffffffffu, s_hi, o);
            sq_hi += __shfl_xor_sync(0xffffffffu, sq_hi, o);
        }
        float m_lo = s_lo * (1.f / 64.f);
        float r_lo = rsqrtf(fmaxf(sq_lo * (1.f / 64.f) - m_lo * m_lo, 0.f) + 1e-5f);
        float m_hi = s_hi * (1.f / 64.f);
        float r_hi = rsqrtf(fmaxf(sq_hi * (1.f / 64.f) - m_hi * m_hi, 0.f) + 1e-5f);
        int row_lo = warpM + g, row_hi = warpM + 8 + g;
        #pragma unroll
        for (int ni = 0; ni < 8; ni++) {
            int c = ni * 8 + t4 * 2;
            float ga0 = sPar[256 + c], be0 = sPar[320 + c];
            float ga1 = sPar[256 + c + 1], be1v = sPar[320 + c + 1];
            sT[c * 136 + row_lo]       = __float2half_rn((acc[ni][0] - m_lo) * r_lo * ga0 + be0);
            sT[(c + 1) * 136 + row_lo] = __float2half_rn((acc[ni][1] - m_lo) * r_lo * ga1 + be1v);
            sT[c * 136 + row_hi]       = __float2half_rn((acc[ni][2] - m_hi) * r_hi * ga0 + be0);
            sT[(c + 1) * 136 + row_hi] = __float2half_rn((acc[ni][3] - m_hi) * r_hi * ga1 + be1v);
        }
    }
    __syncthreads();

    uint32_t* A32 = (uint32_t*)g_A16;
    for (int i = tid; i < 4096; i += 256) {
        int c = i >> 6;
        int d2 = (i & 63) * 2;
        uint32_t v = *(uint32_t*)((char*)sT + (c * 136 + d2) * 2);
        A32[((size_t)b * CTOK + c) * K2U32 + (d0 >> 1) + (d2 >> 1)] = v;
    }
}

// ---------------------------------------------------------------------------
// K5/K7: fp16 mma.sync GEMM   C = relu(A @ W + bias)  (fp32 out, R13 config)
//  4-stage cp.async pipeline, ONE __syncthreads per k-tile.
//  C stores use streaming hint (bufB is written once, read once).
// ---------------------------------------------------------------------------
#define SSTRB 80                 // bytes per smem row (40 fp16)
#define TILEB (128 * SSTRB)      // 10240
#define STAGEB (2 * TILEB)       // 20480  (A tile + B tile)
#define NSTAGE 4
#define GEMM_SMEM (NSTAGE * STAGEB)   // 81920
#define NKT 24                   // 768 / 32

__global__ __launch_bounds__(256, 2) void gemm_f16_kernel(
    const uint4* __restrict__ A16, const uint4* __restrict__ B16,
    const float* __restrict__ bias, float* __restrict__ C)
{
    extern __shared__ char smc[];
    const uint32_t sbase = smem_u32(smc);
    const int tid  = threadIdx.x;
    const int lane = tid & 31;
    const int wid  = tid >> 5;
    const int bx   = blockIdx.x;   // N tile (0..5)
    const int by   = blockIdx.y;   // M tile (0..511)

    const int warpM = (wid & 1) * 64;
    const int warpN = (wid >> 1) * 32;
    const int g  = lane >> 2;      // 0..7
    const int t4 = lane & 3;       // 0..3

    const int lrow = tid >> 1;            // 0..127
    const int ljj  = (tid & 1) * 2;       // 0 or 2
    const uint4* srcA = A16 + ((size_t)(by * 128) + lrow) * K2U4 + ljj;
    const uint4* srcB = B16 + ((size_t)(bx * 128) + lrow) * K2U4 + ljj;
    const uint32_t ldst = lrow * SSTRB + ljj * 16;

    const uint32_t aoff = ((lane & 7) + ((lane >> 3) & 1) * 8) * SSTRB
                        + (lane >> 4) * 16;                       // A (16-row blk)
    const uint32_t boff = (warpN + (lane & 7)) * SSTRB
                        + (lane >> 3) * 16;                       // B (x4: k0..31)

    float acc[4][4][4];
    #pragma unroll
    for (int mi = 0; mi < 4; mi++)
        #pragma unroll
        for (int ni = 0; ni < 4; ni++)
            #pragma unroll
            for (int e = 0; e < 4; e++) acc[mi][ni][e] = 0.f;

    // preload stages 0..2
    #pragma unroll
    for (int s = 0; s < NSTAGE - 1; s++) {
        uint32_t sb = sbase + s * STAGEB + ldst;
        const uint4* pa = srcA + s * 4;
        const uint4* pb = srcB + s * 4;
        cp16(sb, pa);
        cp16(sb + 16, pa + 1);
        cp16(sb + TILEB, pb);
        cp16(sb + TILEB + 16, pb + 1);
        CP_COMMIT();
    }

    for (int t = 0; t < NKT; t++) {
        CP_WAIT(2);
        __syncthreads();

        if (t + NSTAGE - 1 < NKT) {
            uint32_t sb = sbase + ((t + NSTAGE - 1) & (NSTAGE - 1)) * STAGEB + ldst;
            const uint4* pa = srcA + (t + NSTAGE - 1) * 4;
            const uint4* pb = srcB + (t + NSTAGE - 1) * 4;
            cp16(sb, pa);
            cp16(sb + 16, pa + 1);
            cp16(sb + TILEB, pb);
            cp16(sb + TILEB + 16, pb + 1);
        }
        CP_COMMIT();

        const uint32_t Ab = sbase + (t & (NSTAGE - 1)) * STAGEB;
        const uint32_t Bb = Ab + TILEB;

        uint32_t bb[4][4];
        #pragma unroll
        for (int ni = 0; ni < 4; ni++)
            ldsm_x4(bb[ni], Bb + boff + ni * (8 * SSTRB));

        #pragma unroll
        for (int mi = 0; mi < 4; mi++) {
            uint32_t ro = (warpM + mi * 16) * SSTRB + aoff;
            uint32_t a0[4], a1[4];
            ldsm_x4(a0, Ab + ro);          // kk = 0
            ldsm_x4(a1, Ab + ro + 32);     // kk = 1
            #pragma unroll
            for (int ni = 0; ni < 4; ni++)
                mma_f16(acc[mi][ni], a0, bb[ni][0], bb[ni][1]);
            #pragma unroll
            for (int ni = 0; ni < 4; ni++)
                mma_f16(acc[mi][ni], a1, bb[ni][2], bb[ni][3]);
        }
    }

    // epilogue: bias + relu, float2 streaming stores
    #pragma unroll
    for (int mi = 0; mi < 4; mi++) {
        size_t row0 = (size_t)by * 128 + warpM + mi * 16 + g;
        #pragma unroll
        for (int ni = 0; ni < 4; ni++) {
            int col = bx * 128 + warpN + ni * 8 + t4 * 2;
            float b0 = bias[col], b1 = bias[col + 1];
            float2 v0, v1;
            v0.x = fmaxf(acc[mi][ni][0] + b0, 0.f);
            v0.y = fmaxf(acc[mi][ni][1] + b1, 0.f);
            v1.x = fmaxf(acc[mi][ni][2] + b0, 0.f);
            v1.y = fmaxf(acc[mi][ni][3] + b1, 0.f);
            __stcs((float2*)&C[row0 * DDIM + col], v0);
            __stcs((float2*)&C[(row0 + 8) * DDIM + col], v1);
        }
    }
}

// ---------------------------------------------------------------------------
// K6: LayerNorm over 768, fp32 in (streaming read) -> fp16 out.  block=128
// ---------------------------------------------------------------------------
__global__ __launch_bounds__(128) void ln32_to16_kernel(
    const float* __restrict__ in, uint32_t* __restrict__ out16,
    const float* __restrict__ g, const float* __restrict__ be)
{
    size_t row = blockIdx.x;
    int tid = threadIdx.x;
    const float2* p = (const float2*)(in + row * DDIM);
    float2 f0 = __ldcs(&p[tid]);
    float2 f1 = __ldcs(&p[tid + 128]);
    float2 f2 = __ldcs(&p[tid + 256]);
    float s  = f0.x + f0.y + f1.x + f1.y + f2.x + f2.y;
    float sq = f0.x*f0.x + f0.y*f0.y + f1.x*f1.x + f1.y*f1.y + f2.x*f2.x + f2.y*f2.y;
    __shared__ float sh[8];
    #pragma unroll
    for (int o = 16; o; o >>= 1) {
        s  += __shfl_down_sync(0xffffffffu, s, o);
        sq += __shfl_down_sync(0xffffffffu, sq, o);
    }
    if ((tid & 31) == 0) { sh[tid >> 5] = s; sh[4 + (tid >> 5)] = sq; }
    __syncthreads();
    if (tid < 32) {
        float a = (tid < 4) ? sh[tid] : 0.f;
        float c = (tid < 4) ? sh[4 + tid] : 0.f;
        #pragma unroll
        for (int o = 2; o; o >>= 1) {
            a += __shfl_down_sync(0xffffffffu, a, o);
            c += __shfl_down_sync(0xffffffffu, c, o);
        }
        if (tid == 0) { sh[0] = a; sh[1] = c; }
    }
    __syncthreads();
    float mean = sh[0] * (1.f / DDIM);
    float var  = sh[1] * (1.f / DDIM) - mean * mean;
    float rstd = rsqrtf(fmaxf(var, 0.f) + 1e-5f);
    uint32_t* q = out16 + row * K2U32;
    #pragma unroll
    for (int j = 0; j < 3; j++) {
        int pr = tid + j * 128;
        float2 f = (j == 0) ? f0 : (j == 1) ? f1 : f2;
        int c0 = 2 * pr;
        q[pr] = pack2h((f.x - mean) * rstd * g[c0] + be[c0],
                       (f.y - mean) * rstd * g[c0 + 1] + be[c0 + 1]);
    }
}

// ---------------------------------------------------------------------------
// K8: final LayerNorm, fp32 in (streaming read) -> fp32 out.  block=128
// ---------------------------------------------------------------------------
__global__ __launch_bounds__(128) void ln32_to32_kernel(
    const float* __restrict__ in, float* __restrict__ out,
    const float* __restrict__ g, const float* __restrict__ be)
{
    size_t row = blockIdx.x;
    int tid = threadIdx.x;
    const float2* p = (const float2*)(in + row * DDIM);
    float2 f0 = __ldcs(&p[tid]);
    float2 f1 = __ldcs(&p[tid + 128]);
    float2 f2 = __ldcs(&p[tid + 256]);
    float s  = f0.x + f0.y + f1.x + f1.y + f2.x + f2.y;
    float sq = f0.x*f0.x + f0.y*f0.y + f1.x*f1.x + f1.y*f1.y + f2.x*f2.x + f2.y*f2.y;
    __shared__ float sh[8];
    #pragma unroll
    for (int o = 16; o; o >>= 1) {
        s  += __shfl_down_sync(0xffffffffu, s, o);
        sq += __shfl_down_sync(0xffffffffu, sq, o);
    }
    if ((tid & 31) == 0) { sh[tid >> 5] = s; sh[4 + (tid >> 5)] = sq; }
    __syncthreads();
    if (tid < 32) {
        float a = (tid < 4) ? sh[tid] : 0.f;
        float c = (tid < 4) ? sh[4 + tid] : 0.f;
        #pragma unroll
        for (int o = 2; o; o >>= 1) {
            a += __shfl_down_sync(0xffffffffu, a, o);
            c += __shfl_down_sync(0xffffffffu, c, o);
        }
        if (tid == 0) { sh[0] = a; sh[1] = c; }
    }
    __syncthreads();
    float mean = sh[0] * (1.f / DDIM);
    float var  = sh[1] * (1.f / DDIM) - mean * mean;
    float rstd = rsqrtf(fmaxf(var, 0.f) + 1e-5f);
    float2* q = (float2*)(out + row * DDIM);
    #pragma unroll
    for (int j = 0; j < 3; j++) {
        int pr = tid + j * 128;
        float2 f = (j == 0) ? f0 : (j == 1) ? f1 : f2;
        int c0 = 2 * pr;
        float2 w;
        w.x = (f.x - mean) * rstd * g[c0] + be[c0];
        w.y = (f.y - mean) * rstd * g[c0 + 1] + be[c0 + 1];
        q[pr] = w;
    }
}

// ---------------------------------------------------------------------------
// Launch
// ---------------------------------------------------------------------------
extern "C" void kernel_launch(void* const* d_in, const int* in_sizes, int n_in,
                              void* d_out, int out_size)
{
    const float* x_embed = (const float*)d_in[0];
    const float* prompt  = (const float*)d_in[1];
    const float* w1a  = (const float*)d_in[2];
    const float* b1a  = (const float*)d_in[3];
    const float* g1a  = (const float*)d_in[4];
    const float* be1a = (const float*)d_in[5];
    const float* w1b  = (const float*)d_in[6];
    const float* b1b  = (const float*)d_in[7];
    const float* g1b  = (const float*)d_in[8];
    const float* be1b = (const float*)d_in[9];
    const float* w2a  = (const float*)d_in[10];
    const float* b2a  = (const float*)d_in[11];
    const float* g2a  = (const float*)d_in[12];
    const float* be2a = (const float*)d_in[13];
    const float* w2b  = (const float*)d_in[14];
    const float* b2b  = (const float*)d_in[15];
    const float* g2b  = (const float*)d_in[16];
    const float* be2b = (const float*)d_in[17];
    float* out = (float*)d_out;

    int write_aux = (out_size >= OUT_TOTAL) ? 1 : 0;

    float* bufB = nullptr;
    uint4 *A16, *Wa16, *Wb16;
    cudaGetSymbolAddress((void**)&bufB, g_bufB);
    cudaGetSymbolAddress((void**)&A16,  g_A16);
    cudaGetSymbolAddress((void**)&Wa16, g_Wa16);
    cudaGetSymbolAddress((void**)&Wb16, g_Wb16);

    // prompt selection pipeline
    pnorm_kernel<<<POOLN, 256>>>(prompt);
    xmean_norm_kernel<<<BDIM, 256>>>(x_embed);
    sim_topk_kernel<<<BDIM, 256>>>(out, write_aux);
    if (write_aux) reduce_rsim_kernel<<<1, 256>>>(out);

    // weight preps
    wprep_kernel<<<dim3(24, 24), dim3(32, 8)>>>(w2a, (uint32_t*)Wa16);
    wprep_kernel<<<dim3(24, 24), dim3(32, 8)>>>(w2b, (uint32_t*)Wb16);
    w1prep_kernel<<<2, 256>>>(w1a, w1b);

    // fused mlp_1 (tensor-core, M=128/block) -> fp16 activations
    cudaFuncSetAttribute(mlp1_fused_kernel,
                         cudaFuncAttributeMaxDynamicSharedMemorySize, M1_SMEM);
    mlp1_fused_kernel<<<dim3(DDIM / 128, BDIM), 256, M1_SMEM>>>(
        x_embed, prompt, b1a, g1a, be1a, b1b, g1b, be1b);

    // mlp_2: fp16 mma GEMM (fp32 out) + LN stages
    cudaFuncSetAttribute(gemm_f16_kernel,
                         cudaFuncAttributeMaxDynamicSharedMemorySize, GEMM_SMEM);
    dim3 ggrid(DDIM / 128, MROWS / 128);   // (6, 512)
    gemm_f16_kernel<<<ggrid, 256, GEMM_SMEM>>>(A16, Wa16, b2a, bufB);
    ln32_to16_kernel<<<MROWS, 128>>>(bufB, (uint32_t*)A16, g2a, be2a);
    gemm_f16_kernel<<<ggrid, 256, GEMM_SMEM>>>(A16, Wb16, b2b, bufB);
    ln32_to32_kernel<<<MROWS, 128>>>(bufB, out, g2b, be2b);
}

// round 17
// speedup vs baseline: 1.4721x; 1.0016x over previous
#include <cuda_runtime.h>
#include <cuda_fp16.h>
#include <cstdint>
#include <cstddef>

// ---------------------------------------------------------------------------
// Problem constants
// ---------------------------------------------------------------------------
#define BDIM 1024
#define SDIM 64
#define DDIM 768
#define POOLN 30
#define TOPK 4
#define SEQL 68          // TOPK + SDIM
#define CTOK 64
#define MROWS (BDIM*CTOK)    // 65536

#define OFF_RSIM (BDIM*CTOK*DDIM)               // 50331648
#define OFF_SIM  (OFF_RSIM + 1)                 // 50331649
#define OFF_IDX  (OFF_SIM + BDIM*POOLN)         // 50362369
#define OUT_TOTAL (OFF_IDX + BDIM*TOPK)         // 50366465

#define K2U32 384            // u32 per row of an fp16 matrix (768 fp16 / 2)
#define K2U4  96             // uint4 per row

// ---------------------------------------------------------------------------
// Scratch (static __device__ arrays — no runtime allocation)
// ---------------------------------------------------------------------------
__device__ float g_pnorm[POOLN * DDIM];
__device__ int   g_idx[BDIM * TOPK];
__device__ float g_rsum[BDIM];
__device__ uint32_t g_buf16[(size_t)MROWS * K2U32];     // GEMM fp16 outputs
__device__ uint4 g_A16[(size_t)MROWS * K2U4];           // activation fp16
__device__ uint4 g_Wa16[DDIM * K2U4];                   // w2a^T fp16
__device__ uint4 g_Wb16[DDIM * K2U4];                   // w2b^T fp16

// mlp1 pre-transposed split-fp16 weights: (c, s/k) rows, 104 halves/row
#define M1SW  104
#define M1SWB 208
__device__ __align__(16) __half g_W1aTh[64 * M1SW];
__device__ __align__(16) __half g_W1aTl[64 * M1SW];
__device__ __align__(16) __half g_W1bTh[64 * M1SW];
__device__ __align__(16) __half g_W1bTl[64 * M1SW];

// ---------------------------------------------------------------------------
// helpers
// ---------------------------------------------------------------------------
__device__ __forceinline__ uint32_t smem_u32(const void* p) {
    uint32_t a;
    asm("{ .reg .u64 t; cvta.to.shared.u64 t, %1; cvt.u32.u64 %0, t; }"
        : "=r"(a) : "l"(p));
    return a;
}

__device__ __forceinline__ void ldsm_x4(uint32_t* r, uint32_t addr) {
    asm volatile("ldmatrix.sync.aligned.m8n8.x4.shared.b16 {%0,%1,%2,%3}, [%4];"
        : "=r"(r[0]), "=r"(r[1]), "=r"(r[2]), "=r"(r[3]) : "r"(addr));
}

__device__ __forceinline__ void mma_f16(float c[4], const uint32_t a[4],
                                        uint32_t b0, uint32_t b1) {
    asm volatile(
        "mma.sync.aligned.m16n8k16.row.col.f32.f16.f16.f32 "
        "{%0,%1,%2,%3}, {%4,%5,%6,%7}, {%8,%9}, {%0,%1,%2,%3};"
        : "+f"(c[0]), "+f"(c[1]), "+f"(c[2]), "+f"(c[3])
        : "r"(a[0]), "r"(a[1]), "r"(a[2]), "r"(a[3]), "r"(b0), "r"(b1));
}

__device__ __forceinline__ void cp16(uint32_t dst, const void* src) {
    asm volatile("cp.async.cg.shared.global [%0], [%1], 16;" :: "r"(dst), "l"(src));
}
#define CP_COMMIT() asm volatile("cp.async.commit_group;" ::: "memory")
#define CP_WAIT(n)  asm volatile("cp.async.wait_group %0;" :: "n"(n) : "memory")

// pack fp32 pair -> fp16x2
__device__ __forceinline__ uint32_t pack2h(float a, float b) {
    __half2 h = __floats2half2_rn(a, b);
    return *(uint32_t*)&h;
}

// ---------------------------------------------------------------------------
// K1: prompt_norm
// ---------------------------------------------------------------------------
__global__ __launch_bounds__(256) void pnorm_kernel(const float* __restrict__ prompt) {
    int p = blockIdx.x;
    int tid = threadIdx.x;
    const float* row = prompt + (size_t)p * DDIM;
    float v0 = row[tid], v1 = row[tid + 256], v2 = row[tid + 512];
    float ssq = v0 * v0 + v1 * v1 + v2 * v2;
    __shared__ float sh[8];
    #pragma unroll
    for (int o = 16; o; o >>= 1) ssq += __shfl_down_sync(0xffffffffu, ssq, o);
    if ((tid & 31) == 0) sh[tid >> 5] = ssq;
    __syncthreads();
    if (tid < 32) {
        float v = (tid < 8) ? sh[tid] : 0.f;
        #pragma unroll
        for (int o = 4; o; o >>= 1) v += __shfl_down_sync(0xffffffffu, v, o);
        if (tid == 0) sh[0] = v;
    }
    __syncthreads();
    float rn = rsqrtf(fmaxf(sh[0], 1e-12f));
    float* dst = g_pnorm + (size_t)p * DDIM;
    dst[tid]       = v0 * rn;
    dst[tid + 256] = v1 * rn;
    dst[tid + 512] = v2 * rn;
}

// ---------------------------------------------------------------------------
// K2: fused x_mean + l2-normalize + similarity + top-4 + rsum partial.
// grid=B, block=256.  x_norm never leaves smem.
// ---------------------------------------------------------------------------
__global__ __launch_bounds__(256) void xmean_sim_topk_kernel(
    const float* __restrict__ x, float* __restrict__ out, int write_aux)
{
    int b = blockIdx.x;
    int tid = threadIdx.x;
    __shared__ float sx[DDIM];
    __shared__ float ssim[32];
    __shared__ float sh[8];

    float m[3];
    float ssq = 0.f;
    #pragma unroll
    for (int i = 0; i < 3; i++) {
        int d = tid + i * 256;
        float s = 0.f;
        #pragma unroll 8
        for (int si = 0; si < SDIM; si++)
            s += x[((size_t)b * SDIM + si) * DDIM + d];
        m[i] = s * (1.f / SDIM);
        ssq += m[i] * m[i];
    }
    #pragma unroll
    for (int o = 16; o; o >>= 1) ssq += __shfl_down_sync(0xffffffffu, ssq, o);
    if ((tid & 31) == 0) sh[tid >> 5] = ssq;
    __syncthreads();
    if (tid < 32) {
        float v = (tid < 8) ? sh[tid] : 0.f;
        #pragma unroll
        for (int o = 4; o; o >>= 1) v += __shfl_down_sync(0xffffffffu, v, o);
        if (tid == 0) sh[0] = v;
    }
    __syncthreads();
    float rn = rsqrtf(fmaxf(sh[0], 1e-12f));
    #pragma unroll
    for (int i = 0; i < 3; i++)
        sx[tid + i * 256] = m[i] * rn;
    __syncthreads();

    int p = tid >> 3;
    int l8 = tid & 7;
    float acc = 0.f;
    if (p < POOLN) {
        const float* pr = g_pnorm + (size_t)p * DDIM;
        for (int k = l8; k < DDIM; k += 8) acc += sx[k] * pr[k];
    }
    #pragma unroll
    for (int o = 4; o; o >>= 1) acc += __shfl_down_sync(0xffffffffu, acc, o, 8);
    if (l8 == 0 && p < POOLN) ssim[p] = acc;
    __syncthreads();
    if (write_aux && tid < POOLN) out[OFF_SIM + (size_t)b * POOLN + tid] = ssim[tid];
    if (tid == 0) {
        bool used[POOLN];
        #pragma unroll
        for (int i = 0; i < POOLN; i++) used[i] = false;
        float rs = 0.f;
        for (int k = 0; k < TOPK; k++) {
            int best = 0;
            float bv = -3.4e38f;
            for (int pp = 0; pp < POOLN; pp++) {
                if (!used[pp] && ssim[pp] > bv) { bv = ssim[pp]; best = pp; }
            }
            used[best] = true;
            g_idx[b * TOPK + k] = best;
            if (write_aux) out[OFF_IDX + (size_t)b * TOPK + k] = (float)best;
            rs += bv;
        }
        g_rsum[b] = rs;
    }
}

// ---------------------------------------------------------------------------
// K3b: reduce_sim scalar
// ---------------------------------------------------------------------------
__global__ __launch_bounds__(256) void reduce_rsim_kernel(float* __restrict__ out) {
    int tid = threadIdx.x;
    float v = g_rsum[tid] + g_rsum[tid + 256] + g_rsum[tid + 512] + g_rsum[tid + 768];
    __shared__ float sh[8];
    #pragma unroll
    for (int o = 16; o; o >>= 1) v += __shfl_down_sync(0xffffffffu, v, o);
    if ((tid & 31) == 0) sh[tid >> 5] = v;
    __syncthreads();
    if (tid < 32) {
        float w = (tid < 8) ? sh[tid] : 0.f;
        #pragma unroll
        for (int o = 4; o; o >>= 1) w += __shfl_down_sync(0xffffffffu, w, o);
        if (tid == 0) out[OFF_RSIM] = w * (1.f / BDIM);
    }
}

// ---------------------------------------------------------------------------
// K-wprep: transpose 768x768 weight into fp16 pairs.  grid (24,24), blk (32,8)
// ---------------------------------------------------------------------------
__global__ __launch_bounds__(256) void wprep_kernel(
    const float* __restrict__ W, uint32_t* __restrict__ W16)
{
    __shared__ float t[32][33];
    int bxn = blockIdx.x;   // n tile
    int byk = blockIdx.y;   // k tile
    int tx = threadIdx.x, ty = threadIdx.y;
    #pragma unroll
    for (int i = 0; i < 4; i++) {
        int k = byk * 32 + ty + i * 8;
        t[ty + i * 8][tx] = W[(size_t)k * DDIM + bxn * 32 + tx];
    }
    __syncthreads();
    int tid = ty * 32 + tx;
    #pragma unroll
    for (int q = 0; q < 2; q++) {
        int idx = tid + q * 256;
        int nn = idx >> 4;         // 0..31
        int p  = idx & 15;         // k-pair within tile
        size_t o = (size_t)(bxn * 32 + nn) * K2U32 + byk * 16 + p;
        W16[o] = pack2h(t[2 * p][nn], t[2 * p + 1][nn]);
    }
}

// ---------------------------------------------------------------------------
// K-w1prep: transpose + fp16-split mlp_1 weights into (c, s) rows of 104.
// grid=2 (0: w1a, 1: w1b), block=256.
// ---------------------------------------------------------------------------
__global__ __launch_bounds__(256) void w1prep_kernel(
    const float* __restrict__ w1a, const float* __restrict__ w1b)
{
    int sel = blockIdx.x;
    const float* src = sel ? w1b : w1a;
    int K = sel ? 64 : SEQL;
    __half* dh = sel ? g_W1bTh : g_W1aTh;
    __half* dl = sel ? g_W1bTl : g_W1aTl;
    for (int i = threadIdx.x; i < 64 * M1SW; i += 256) {
        int c = i / M1SW, s = i % M1SW;
        float v = (s < K) ? src[s * 64 + c] : 0.f;
        __half h = __float2half_rn(v);
        dh[i] = h;
        dl[i] = __float2half_rn(v - __half2float(h));
    }
}

// ---------------------------------------------------------------------------
// K4: fused mlp_1 (token mixing) — tensor-core, M=128 per block.
// grid = (6, B), block=256, 8 warps of 16(M)x64(N).
// LayerNorm fully in registers (quad shfl).  3 __syncthreads per block.
// ---------------------------------------------------------------------------
#define M1_A_H  0
#define M1_A_L  26624
#define M1_WA_H 53248
#define M1_WA_L 66560
#define M1_WB_H 79872
#define M1_WB_L 93184
#define M1_PAR  106496
#define M1_SMEM 108032
#define M1_ST   M1_WA_H          // 17408 needed, 26624 available

__global__ __launch_bounds__(256, 2) void mlp1_fused_kernel(
    const float* __restrict__ x_embed, const float* __restrict__ prompt,
    const float* __restrict__ b1a, const float* __restrict__ g1a,
    const float* __restrict__ be1a,
    const float* __restrict__ b1b, const float* __restrict__ g1b,
    const float* __restrict__ be1b)
{
    extern __shared__ char smx[];
    const uint32_t sbase = smem_u32(smx);
    __half* smAh = (__half*)(smx + M1_A_H);
    __half* smAl = (__half*)(smx + M1_A_L);
    float*  sPar = (float*)(smx + M1_PAR);
    __half* sT   = (__half*)(smx + M1_ST);

    const int b  = blockIdx.y;
    const int d0 = blockIdx.x * 128;
    const int tid = threadIdx.x;
    const int lane = tid & 31, wid = tid >> 5;
    const int warpM = wid * 16;
    const int g = lane >> 2, t4 = lane & 3;

    if (tid < 64) {
        sPar[tid]       = b1a[tid];
        sPar[64 + tid]  = g1a[tid];
        sPar[128 + tid] = be1a[tid];
        sPar[192 + tid] = b1b[tid];
        sPar[256 + tid] = g1b[tid];
        sPar[320 + tid] = be1b[tid];
    }
    {
        const uint4* s0 = (const uint4*)g_W1aTh;
        const uint4* s1 = (const uint4*)g_W1aTl;
        const uint4* s2 = (const uint4*)g_W1bTh;
        const uint4* s3 = (const uint4*)g_W1bTl;
        uint4* d0_ = (uint4*)(smx + M1_WA_H);
        uint4* d1_ = (uint4*)(smx + M1_WA_L);
        uint4* d2_ = (uint4*)(smx + M1_WB_H);
        uint4* d3_ = (uint4*)(smx + M1_WB_L);
        for (int i = tid; i < 832; i += 256) {
            d0_[i] = s0[i]; d1_[i] = s1[i]; d2_[i] = s2[i]; d3_[i] = s3[i];
        }
    }
    for (int i = tid; i < 128 * 28; i += 256) {
        int dd = i / 28, s = 68 + i % 28;
        smAh[dd * M1SW + s] = __ushort_as_half((unsigned short)0);
        smAl[dd * M1SW + s] = __ushort_as_half((unsigned short)0);
    }
    for (int i = tid; i < SEQL * 128; i += 256) {
        int s = i >> 7, dd = i & 127;
        float v;
        if (s < TOPK)
            v = prompt[(size_t)g_idx[b * TOPK + s] * DDIM + d0 + dd];
        else
            v = x_embed[((size_t)b * SDIM + (s - TOPK)) * DDIM + d0 + dd];
        __half h = __float2half_rn(v);
        smAh[dd * M1SW + s] = h;
        smAl[dd * M1SW + s] = __float2half_rn(v - __half2float(h));
    }
    __syncthreads();

    const uint32_t aoff = ((lane & 7) + ((lane >> 3) & 1) * 8) * M1SWB
                        + (lane >> 4) * 16;
    const uint32_t boff = (lane & 7) * M1SWB + (lane >> 3) * 16;
    const uint32_t sAh = sbase + M1_A_H + warpM * M1SWB;
    const uint32_t sAl = sbase + M1_A_L + warpM * M1SWB;

    float acc[8][4];
    #pragma unroll
    for (int ni = 0; ni < 8; ni++)
        #pragma unroll
        for (int e = 0; e < 4; e++) acc[ni][e] = 0.f;

    // ---- GEMM1: H1[d][c] = A^T @ W1a  (K=96 padded), 3-term split ----
    #pragma unroll
    for (int kb = 0; kb < 3; kb++) {
        uint32_t ah0[4], ah1[4], al0[4], al1[4];
        ldsm_x4(ah0, sAh + aoff + kb * 64);
        ldsm_x4(ah1, sAh + aoff + kb * 64 + 32);
        ldsm_x4(al0, sAl + aoff + kb * 64);
        ldsm_x4(al1, sAl + aoff + kb * 64 + 32);
        #pragma unroll
        for (int ni = 0; ni < 8; ni++) {
            uint32_t bh[4], bl[4];
            uint32_t ba = ni * 8 * M1SWB + boff + kb * 64;
            ldsm_x4(bh, sbase + M1_WA_H + ba);
            ldsm_x4(bl, sbase + M1_WA_L + ba);
            mma_f16(acc[ni], ah0, bh[0], bh[1]);
            mma_f16(acc[ni], ah0, bl[0], bl[1]);
            mma_f16(acc[ni], al0, bh[0], bh[1]);
            mma_f16(acc[ni], ah1, bh[2], bh[3]);
            mma_f16(acc[ni], ah1, bl[2], bl[3]);
            mma_f16(acc[ni], al1, bh[2], bh[3]);
        }
    }

    // ---- epilogue 1: bias+relu+LN in regs -> split fp16 back into A tiles ----
    {
        float s_lo = 0.f, sq_lo = 0.f, s_hi = 0.f, sq_hi = 0.f;
        #pragma unroll
        for (int ni = 0; ni < 8; ni++) {
            int c = ni * 8 + t4 * 2;
            float b0 = sPar[c], b1v = sPar[c + 1];
            acc[ni][0] = fmaxf(acc[ni][0] + b0, 0.f);
            acc[ni][1] = fmaxf(acc[ni][1] + b1v, 0.f);
            acc[ni][2] = fmaxf(acc[ni][2] + b0, 0.f);
            acc[ni][3] = fmaxf(acc[ni][3] + b1v, 0.f);
            s_lo += acc[ni][0] + acc[ni][1];
            sq_lo += acc[ni][0] * acc[ni][0] + acc[ni][1] * acc[ni][1];
            s_hi += acc[ni][2] + acc[ni][3];
            sq_hi += acc[ni][2] * acc[ni][2] + acc[ni][3] * acc[ni][3];
        }
        #pragma unroll
        for (int o = 1; o <= 2; o <<= 1) {
            s_lo  += __shfl_xor_sync(0xffffffffu, s_lo, o);
            sq_lo += __shfl_xor_sync(0xffffffffu, sq_lo, o);
            s_hi  += __shfl_xor_sync(0xffffffffu, s_hi, o);
            sq_hi += __shfl_xor_sync(0xffffffffu, sq_hi, o);
        }
        float m_lo = s_lo * (1.f / 64.f);
        float r_lo = rsqrtf(fmaxf(sq_lo * (1.f / 64.f) - m_lo * m_lo, 0.f) + 1e-5f);
        float m_hi = s_hi * (1.f / 64.f);
        float r_hi = rsqrtf(fmaxf(sq_hi * (1.f / 64.f) - m_hi * m_hi, 0.f) + 1e-5f);
        int row_lo = warpM + g, row_hi = warpM + 8 + g;
        #pragma unroll
        for (int ni = 0; ni < 8; ni++) {
            int c = ni * 8 + t4 * 2;
            float ga0 = sPar[64 + c], be0 = sPar[128 + c];
            float ga1 = sPar[64 + c + 1], be1v = sPar[128 + c + 1];
            float y0 = (acc[ni][0] - m_lo) * r_lo * ga0 + be0;
            float y1 = (acc[ni][1] - m_lo) * r_lo * ga1 + be1v;
            float y2 = (acc[ni][2] - m_hi) * r_hi * ga0 + be0;
            float y3 = (acc[ni][3] - m_hi) * r_hi * ga1 + be1v;
            uint32_t h01 = pack2h(y0, y1);
            __half2 hh = *(__half2*)&h01;
            uint32_t l01 = pack2h(y0 - __half2float(hh.x), y1 - __half2float(hh.y));
            uint32_t h23 = pack2h(y2, y3);
            __half2 hh2 = *(__half2*)&h23;
            uint32_t l23 = pack2h(y2 - __half2float(hh2.x), y3 - __half2float(hh2.y));
            *(uint32_t*)((char*)smAh + row_lo * M1SWB + c * 2) = h01;
            *(uint32_t*)((char*)smAl + row_lo * M1SWB + c * 2) = l01;
            *(uint32_t*)((char*)smAh + row_hi * M1SWB + c * 2) = h23;
            *(uint32_t*)((char*)smAl + row_hi * M1SWB + c * 2) = l23;
        }
    }
    __syncthreads();

    // ---- GEMM2: H2 = H1 @ W1b  (K=64), 3-term split ----
    #pragma unroll
    for (int ni = 0; ni < 8; ni++)
        #pragma unroll
        for (int e = 0; e < 4; e++) acc[ni][e] = 0.f;
    #pragma unroll
    for (int kb = 0; kb < 2; kb++) {
        uint32_t ah0[4], ah1[4], al0[4], al1[4];
        ldsm_x4(ah0, sAh + aoff + kb * 64);
        ldsm_x4(ah1, sAh + aoff + kb * 64 + 32);
        ldsm_x4(al0, sAl + aoff + kb * 64);
        ldsm_x4(al1, sAl + aoff + kb * 64 + 32);
        #pragma unroll
        for (int ni = 0; ni < 8; ni++) {
            uint32_t bh[4], bl[4];
            uint32_t ba = ni * 8 * M1SWB + boff + kb * 64;
            ldsm_x4(bh, sbase + M1_WB_H + ba);
            ldsm_x4(bl, sbase + M1_WB_L + ba);
            mma_f16(acc[ni], ah0, bh[0], bh[1]);
            mma_f16(acc[ni], ah0, bl[0], bl[1]);
            mma_f16(acc[ni], al0, bh[0], bh[1]);
            mma_f16(acc[ni], ah1, bh[2], bh[3]);
            mma_f16(acc[ni], ah1, bl[2], bl[3]);
            mma_f16(acc[ni], al1, bh[2], bh[3]);
        }
    }

    // ---- epilogue 2: bias+relu+LN in regs -> fp16 into transpose stage ----
    {
        float s_lo = 0.f, sq_lo = 0.f, s_hi = 0.f, sq_hi = 0.f;
        #pragma unroll
        for (int ni = 0; ni < 8; ni++) {
            int c = ni * 8 + t4 * 2;
            float b0 = sPar[192 + c], b1v = sPar[192 + c + 1];
            acc[ni][0] = fmaxf(acc[ni][0] + b0, 0.f);
            acc[ni][1] = fmaxf(acc[ni][1] + b1v, 0.f);
            acc[ni][2] = fmaxf(acc[ni][2] + b0, 0.f);
            acc[ni][3] = fmaxf(acc[ni][3] + b1v, 0.f);
            s_lo += acc[ni][0] + acc[ni][1];
            sq_lo += acc[ni][0] * acc[ni][0] + acc[ni][1] * acc[ni][1];
            s_hi += acc[ni][2] + acc[ni][3];
            sq_hi += acc[ni][2] * acc[ni][2] + acc[ni][3] * acc[ni][3];
        }
        #pragma unroll
        for (int o = 1; o <= 2; o <<= 1) {
            s_lo  += __shfl_xor_sync(0xffffffffu, s_lo, o);
            sq_lo += __shfl_xor_sync(0xffffffffu, sq_lo, o);
            s_hi  += __shfl_xor_sync(0xffffffffu, s_hi, o);
            sq_hi += __shfl_xor_sync(0xffffffffu, sq_hi, o);
        }
        float m_lo = s_lo * (1.f / 64.f);
        float r_lo = rsqrtf(fmaxf(sq_lo * (1.f / 64.f) - m_lo * m_lo, 0.f) + 1e-5f);
        float m_hi = s_hi * (1.f / 64.f);
        float r_hi = rsqrtf(fmaxf(sq_hi * (1.f / 64.f) - m_hi * m_hi, 0.f) + 1e-5f);
        int row_lo = warpM + g, row_hi = warpM + 8 + g;
        #pragma unroll
        for (int ni = 0; ni < 8; ni++) {
            int c = ni * 8 + t4 * 2;
            float ga0 = sPar[256 + c], be0 = sPar[320 + c];
            float ga1 = sPar[256 + c + 1], be1v = sPar[320 + c + 1];
            sT[c * 136 + row_lo]       = __float2half_rn((acc[ni][0] - m_lo) * r_lo * ga0 + be0);
            sT[(c + 1) * 136 + row_lo] = __float2half_rn((acc[ni][1] - m_lo) * r_lo * ga1 + be1v);
            sT[c * 136 + row_hi]       = __float2half_rn((acc[ni][2] - m_hi) * r_hi * ga0 + be0);
            sT[(c + 1) * 136 + row_hi] = __float2half_rn((acc[ni][3] - m_hi) * r_hi * ga1 + be1v);
        }
    }
    __syncthreads();

    uint32_t* A32 = (uint32_t*)g_A16;
    for (int i = tid; i < 4096; i += 256) {
        int c = i >> 6;
        int d2 = (i & 63) * 2;
        uint32_t v = *(uint32_t*)((char*)sT + (c * 136 + d2) * 2);
        A32[((size_t)b * CTOK + c) * K2U32 + (d0 >> 1) + (d2 >> 1)] = v;
    }
}

// ---------------------------------------------------------------------------
// K5/K7: fp16 mma.sync GEMM   C16 = fp16(relu(A @ W + bias))
//  4-stage cp.async pipeline, ONE __syncthreads per k-tile.
//  Epilogue stages C tile in smem -> fully coalesced 128B-line fp16 stores
//  (fixes R14's partial-sector RMW regression while keeping the traffic win).
// ---------------------------------------------------------------------------
#define SSTRB 80                 // bytes per smem row (40 fp16)
#define TILEB (128 * SSTRB)      // 10240
#define STAGEB (2 * TILEB)       // 20480  (A tile + B tile)
#define NSTAGE 4
#define GEMM_SMEM (NSTAGE * STAGEB)   // 81920
#define NKT 24                   // 768 / 32
#define CSTR 68                  // u32 stride of staged C tile (272B rows)

__global__ __launch_bounds__(256, 2) void gemm_f16_kernel(
    const uint4* __restrict__ A16, const uint4* __restrict__ B16,
    const float* __restrict__ bias, uint32_t* __restrict__ C16)
{
    extern __shared__ char smc[];
    const uint32_t sbase = smem_u32(smc);
    const int tid  = threadIdx.x;
    const int lane = tid & 31;
    const int wid  = tid >> 5;
    const int bx   = blockIdx.x;   // N tile (0..5)
    const int by   = blockIdx.y;   // M tile (0..511)

    const int warpM = (wid & 1) * 64;
    const int warpN = (wid >> 1) * 32;
    const int g  = lane >> 2;      // 0..7
    const int t4 = lane & 3;       // 0..3

    const int lrow = tid >> 1;            // 0..127
    const int ljj  = (tid & 1) * 2;       // 0 or 2
    const uint4* srcA = A16 + ((size_t)(by * 128) + lrow) * K2U4 + ljj;
    const uint4* srcB = B16 + ((size_t)(bx * 128) + lrow) * K2U4 + ljj;
    const uint32_t ldst = lrow * SSTRB + ljj * 16;

    const uint32_t aoff = ((lane & 7) + ((lane >> 3) & 1) * 8) * SSTRB
                        + (lane >> 4) * 16;                       // A (16-row blk)
    const uint32_t boff = (warpN + (lane & 7)) * SSTRB
                        + (lane >> 3) * 16;                       // B (x4: k0..31)

    float acc[4][4][4];
    #pragma unroll
    for (int mi = 0; mi < 4; mi++)
        #pragma unroll
        for (int ni = 0; ni < 4; ni++)
            #pragma unroll
            for (int e = 0; e < 4; e++) acc[mi][ni][e] = 0.f;

    // preload stages 0..2
    #pragma unroll
    for (int s = 0; s < NSTAGE - 1; s++) {
        uint32_t sb = sbase + s * STAGEB + ldst;
        const uint4* pa = srcA + s * 4;
        const uint4* pb = srcB + s * 4;
        cp16(sb, pa);
        cp16(sb + 16, pa + 1);
        cp16(sb + TILEB, pb);
        cp16(sb + TILEB + 16, pb + 1);
        CP_COMMIT();
    }

    for (int t = 0; t < NKT; t++) {
        CP_WAIT(2);
        __syncthreads();

        if (t + NSTAGE - 1 < NKT) {
            uint32_t sb = sbase + ((t + NSTAGE - 1) & (NSTAGE - 1)) * STAGEB + ldst;
            const uint4* pa = srcA + (t + NSTAGE - 1) * 4;
            const uint4* pb = srcB + (t + NSTAGE - 1) * 4;
            cp16(sb, pa);
            cp16(sb + 16, pa + 1);
            cp16(sb + TILEB, pb);
            cp16(sb + TILEB + 16, pb + 1);
        }
        CP_COMMIT();

        const uint32_t Ab = sbase + (t & (NSTAGE - 1)) * STAGEB;
        const uint32_t Bb = Ab + TILEB;

        uint32_t bb[4][4];
        #pragma unroll
        for (int ni = 0; ni < 4; ni++)
            ldsm_x4(bb[ni], Bb + boff + ni * (8 * SSTRB));

        #pragma unroll
        for (int mi = 0; mi < 4; mi++) {
            uint32_t ro = (warpM + mi * 16) * SSTRB + aoff;
            uint32_t a0[4], a1[4];
            ldsm_x4(a0, Ab + ro);          // kk = 0
            ldsm_x4(a1, Ab + ro + 32);     // kk = 1
            #pragma unroll
            for (int ni = 0; ni < 4; ni++)
                mma_f16(acc[mi][ni], a0, bb[ni][0], bb[ni][1]);
            #pragma unroll
            for (int ni = 0; ni < 4; ni++)
                mma_f16(acc[mi][ni], a1, bb[ni][2], bb[ni][3]);
        }
    }

    // ---- epilogue: bias+relu -> fp16 smem stage (conflict-free writes) ----
    __syncthreads();   // all warps done reading stage buffers
    uint32_t* cs = (uint32_t*)smc;
    #pragma unroll
    for (int mi = 0; mi < 4; mi++) {
        int r0 = warpM + mi * 16 + g;
        #pragma unroll
        for (int ni = 0; ni < 4; ni++) {
            int col = bx * 128 + warpN + ni * 8 + t4 * 2;
            float b0 = bias[col], b1 = bias[col + 1];
            int cu = (warpN >> 1) + ni * 4 + t4;
            cs[r0 * CSTR + cu] = pack2h(fmaxf(acc[mi][ni][0] + b0, 0.f),
                                        fmaxf(acc[mi][ni][1] + b1, 0.f));
            cs[(r0 + 8) * CSTR + cu] = pack2h(fmaxf(acc[mi][ni][2] + b0, 0.f),
                                              fmaxf(acc[mi][ni][3] + b1, 0.f));
        }
    }
    __syncthreads();
    // ---- coalesced streaming store: 2 threads per row, 32 u32 each ----
    {
        int r = tid >> 1, j = tid & 1;
        const uint32_t* src = cs + r * CSTR + j * 32;
        uint4* dst = (uint4*)(C16 + (size_t)(by * 128 + r) * K2U32 + bx * 64 + j * 32);
        #pragma unroll
        for (int i = 0; i < 8; i++)
            __stcs(&dst[i], *(const uint4*)(src + i * 4));
    }
}

// ---------------------------------------------------------------------------
// K6: LayerNorm over 768, fp16 in -> fp16 out (feeds next GEMM).  block=128
// ---------------------------------------------------------------------------
__global__ __launch_bounds__(128) void ln16_to16_kernel(
    const uint32_t* __restrict__ in16, uint32_t* __restrict__ out16,
    const float* __restrict__ g, const float* __restrict__ be)
{
    size_t row = blockIdx.x;
    int tid = threadIdx.x;
    const uint32_t* p = in16 + row * K2U32;
    uint32_t u0 = __ldcs(&p[tid]), u1 = __ldcs(&p[tid + 128]), u2 = __ldcs(&p[tid + 256]);
    float2 f0 = __half22float2(*(__half2*)&u0);
    float2 f1 = __half22float2(*(__half2*)&u1);
    float2 f2 = __half22float2(*(__half2*)&u2);
    float s  = f0.x + f0.y + f1.x + f1.y + f2.x + f2.y;
    float sq = f0.x*f0.x + f0.y*f0.y + f1.x*f1.x + f1.y*f1.y + f2.x*f2.x + f2.y*f2.y;
    __shared__ float sh[8];
    #pragma unroll
    for (int o = 16; o; o >>= 1) {
        s  += __shfl_down_sync(0xffffffffu, s, o);
        sq += __shfl_down_sync(0xffffffffu, sq, o);
    }
    if ((tid & 31) == 0) { sh[tid >> 5] = s; sh[4 + (tid >> 5)] = sq; }
    __syncthreads();
    if (tid < 32) {
        float a = (tid < 4) ? sh[tid] : 0.f;
        float c = (tid < 4) ? sh[4 + tid] : 0.f;
        #pragma unroll
        for (int o = 2; o; o >>= 1) {
            a += __shfl_down_sync(0xffffffffu, a, o);
            c += __shfl_down_sync(0xffffffffu, c, o);
        }
        if (tid == 0) { sh[0] = a; sh[1] = c; }
    }
    __syncthreads();
    float mean = sh[0] * (1.f / DDIM);
    float var  = sh[1] * (1.f / DDIM) - mean * mean;
    float rstd = rsqrtf(fmaxf(var, 0.f) + 1e-5f);
    uint32_t* q = out16 + row * K2U32;
    #pragma unroll
    for (int j = 0; j < 3; j++) {
        int pr = tid + j * 128;
        float2 f = (j == 0) ? f0 : (j == 1) ? f1 : f2;
        int c0 = 2 * pr;
        q[pr] = pack2h((f.x - mean) * rstd * g[c0] + be[c0],
                       (f.y - mean) * rstd * g[c0 + 1] + be[c0 + 1]);
    }
}

// ---------------------------------------------------------------------------
// K8: final LayerNorm, fp16 in -> fp32 out.  block=128
// ---------------------------------------------------------------------------
__global__ __launch_bounds__(128) void ln16_to32_kernel(
    const uint32_t* __restrict__ in16, float* __restrict__ out,
    const float* __restrict__ g, const float* __restrict__ be)
{
    size_t row = blockIdx.x;
    int tid = threadIdx.x;
    const uint32_t* p = in16 + row * K2U32;
    uint32_t u0 = __ldcs(&p[tid]), u1 = __ldcs(&p[tid + 128]), u2 = __ldcs(&p[tid + 256]);
    float2 f0 = __half22float2(*(__half2*)&u0);
    float2 f1 = __half22float2(*(__half2*)&u1);
    float2 f2 = __half22float2(*(__half2*)&u2);
    float s  = f0.x + f0.y + f1.x + f1.y + f2.x + f2.y;
    float sq = f0.x*f0.x + f0.y*f0.y + f1.x*f1.x + f1.y*f1.y + f2.x*f2.x + f2.y*f2.y;
    __shared__ float sh[8];
    #pragma unroll
    for (int o = 16; o; o >>= 1) {
        s  += __shfl_down_sync(0xffffffffu, s, o);
        sq += __shfl_down_sync(0xffffffffu, sq, o);
    }
    if ((tid & 31) == 0) { sh[tid >> 5] = s; sh[4 + (tid >> 5)] = sq; }
    __syncthreads();
    if (tid < 32) {
        float a = (tid < 4) ? sh[tid] : 0.f;
        float c = (tid < 4) ? sh[4 + tid] : 0.f;
        #pragma unroll
        for (int o = 2; o; o >>= 1) {
            a += __shfl_down_sync(0xffffffffu, a, o);
            c += __shfl_down_sync(0xffffffffu, c, o);
        }
        if (tid == 0) { sh[0] = a; sh[1] = c; }
    }
    __syncthreads();
    float mean = sh[0] * (1.f / DDIM);
    float var  = sh[1] * (1.f / DDIM) - mean * mean;
    float rstd = rsqrtf(fmaxf(var, 0.f) + 1e-5f);
    float2* q = (float2*)(out + row * DDIM);
    #pragma unroll
    for (int j = 0; j < 3; j++) {
        int pr = tid + j * 128;
        float2 f = (j == 0) ? f0 : (j == 1) ? f1 : f2;
        int c0 = 2 * pr;
        float2 w;
        w.x = (f.x - mean) * rstd * g[c0] + be[c0];
        w.y = (f.y - mean) * rstd * g[c0 + 1] + be[c0 + 1];
        q[pr] = w;
    }
}

// ---------------------------------------------------------------------------
// Launch
// ---------------------------------------------------------------------------
extern "C" void kernel_launch(void* const* d_in, const int* in_sizes, int n_in,
                              void* d_out, int out_size)
{
    const float* x_embed = (const float*)d_in[0];
    const float* prompt  = (const float*)d_in[1];
    const float* w1a  = (const float*)d_in[2];
    const float* b1a  = (const float*)d_in[3];
    const float* g1a  = (const float*)d_in[4];
    const float* be1a = (const float*)d_in[5];
    const float* w1b  = (const float*)d_in[6];
    const float* b1b  = (const float*)d_in[7];
    const float* g1b  = (const float*)d_in[8];
    const float* be1b = (const float*)d_in[9];
    const float* w2a  = (const float*)d_in[10];
    const float* b2a  = (const float*)d_in[11];
    const float* g2a  = (const float*)d_in[12];
    const float* be2a = (const float*)d_in[13];
    const float* w2b  = (const float*)d_in[14];
    const float* b2b  = (const float*)d_in[15];
    const float* g2b  = (const float*)d_in[16];
    const float* be2b = (const float*)d_in[17];
    float* out = (float*)d_out;

    int write_aux = (out_size >= OUT_TOTAL) ? 1 : 0;

    uint32_t* buf16 = nullptr;
    uint4 *A16, *Wa16, *Wb16;
    cudaGetSymbolAddress((void**)&buf16, g_buf16);
    cudaGetSymbolAddress((void**)&A16,  g_A16);
    cudaGetSymbolAddress((void**)&Wa16, g_Wa16);
    cudaGetSymbolAddress((void**)&Wb16, g_Wb16);

    // prompt selection pipeline (fused)
    pnorm_kernel<<<POOLN, 256>>>(prompt);
    xmean_sim_topk_kernel<<<BDIM, 256>>>(x_embed, out, write_aux);
    if (write_aux) reduce_rsim_kernel<<<1, 256>>>(out);

    // weight preps
    wprep_kernel<<<dim3(24, 24), dim3(32, 8)>>>(w2a, (uint32_t*)Wa16);
    wprep_kernel<<<dim3(24, 24), dim3(32, 8)>>>(w2b, (uint32_t*)Wb16);
    w1prep_kernel<<<2, 256>>>(w1a, w1b);

    // fused mlp_1 (tensor-core, M=128/block) -> fp16 activations
    cudaFuncSetAttribute(mlp1_fused_kernel,
                         cudaFuncAttributeMaxDynamicSharedMemorySize, M1_SMEM);
    mlp1_fused_kernel<<<dim3(DDIM / 128, BDIM), 256, M1_SMEM>>>(
        x_embed, prompt, b1a, g1a, be1a, b1b, g1b, be1b);

    // mlp_2: fp16 mma GEMM (staged fp16 out) + LN stages (fp16 in)
    cudaFuncSetAttribute(gemm_f16_kernel,
                         cudaFuncAttributeMaxDynamicSharedMemorySize, GEMM_SMEM);
    dim3 ggrid(DDIM / 128, MROWS / 128);   // (6, 512)
    gemm_f16_kernel<<<ggrid, 256, GEMM_SMEM>>>(A16, Wa16, b2a, buf16);
    ln16_to16_kernel<<<MROWS, 128>>>(buf16, (uint32_t*)A16, g2a, be2a);
    gemm_f16_kernel<<<ggrid, 256, GEMM_SMEM>>>(A16, Wb16, b2b, buf16);
    ln16_to32_kernel<<<MROWS, 128>>>(buf16, out, g2b, be2b);
}